// round 10
// baseline (speedup 1.0000x reference)
#include <cuda_runtime.h>
#include <cstdint>

#define TOPK      2000
#define NMS_THR   0.5f
#define MAXN      200000
#define MAXG      128
#define HBINS     65536
#define CAP       8192
#define CBLK      32          // ceil(TOPK/64)
#define BM        128         // proposals per block
#define NCELLMAX  128         // max grid cells (11x7=77 typical)
#define CELLCAP   24          // max GT entries per cell

typedef unsigned long long ull;

// ---------------- scratch (no allocation allowed) ----------------
__device__ float               g_score[MAXN];
__device__ unsigned char       g_cls[MAXN];
__device__ __align__(16) int   g_hist[HBINS];    // zero at load; re-zeroed in compact
__device__ int                 g_candcount;      // zero at load; reset in sort
__device__ int                 g_binB;
__device__ ull                 g_cand[CAP];
__device__ int                 g_topidx[TOPK];
__device__ float4              g_topboxes[TOPK];
__device__ ull                 g_mask[TOPK * CBLK];

// =================== K1a: scores only (branch A head) =====================
__global__ void __launch_bounds__(BM) score_kernel(
        const float*  __restrict__ cls,
        int N, int C)
{
    extern __shared__ float scls[];       // BM*21 floats (stride 21 -> conflict-free)
    int tid = threadIdx.x;
    int n0  = blockIdx.x * BM;
    int rows = min(BM, N - n0);
    if (rows <= 0) return;

    const float* cbase = cls + (size_t)n0 * C;
    if (C == 21 && rows == BM) {
        // BM*21/4 = 672 float4, base offset blk*10752B is 16B-aligned
        const float4* c4 = (const float4*)cbase;
        float4* s4 = (float4*)scls;
        #pragma unroll
        for (int e = 0; e < (BM * 21 / 4) / BM; e++)           // 5 full rounds
            s4[tid + e * BM] = c4[tid + e * BM];
        {   int idx = tid + (BM * 21 / 4 / BM) * BM;           // remainder 32
            if (idx < BM * 21 / 4) s4[idx] = c4[idx];
        }
    } else {
        int total = rows * C;
        for (int idx = tid; idx < total; idx += BM) {
            int r = idx / C;
            scls[r * 21 + (idx - r * C)] = cbase[idx];
        }
    }
    __syncthreads();

    int n = n0 + tid;
    if (n >= N) return;

    const float* cr = scls + tid * 21;
    float m = cr[0], bl = -1e30f; int bc = 1;
    #pragma unroll
    for (int c = 1; c < 21; c++) {
        float v = cr[c];
        m = fmaxf(m, v);
        if (v > bl) { bl = v; bc = c; }
    }
    float Z = 0.f;
    #pragma unroll
    for (int c = 0; c < 21; c++) Z += __expf(cr[c] - m);
    float score = __fdividef(__expf(bl - m), Z);

    g_score[n] = score;
    g_cls[n]   = (unsigned char)bc;
    atomicAdd(&g_hist[__float_as_uint(score) >> 16], 1);
}

// =================== K1b: reg_targets (independent branch B) ==============
__global__ void __launch_bounds__(BM) regtarget_kernel(
        const float4* __restrict__ prop,
        const float4* __restrict__ gt,
        const int* __restrict__ ihp,
        const int* __restrict__ iwp,
        float4* __restrict__ out,         // rows TOPK..TOPK+N
        int N, int G)
{
    __shared__ float4        sgtb[MAXG];
    __shared__ float         sga[MAXG];
    __shared__ int           scnt[NCELLMAX];
    __shared__ unsigned char slist[NCELLMAX * CELLCAP];
    __shared__ int           soverflow;

    int tid = threadIdx.x;
    int n0  = blockIdx.x * BM;

    int vi = ihp[0];
    float H = (vi > 0 && vi < 1000000) ? (float)vi : __int_as_float(vi);
    vi = iwp[0];
    float W = (vi > 0 && vi < 1000000) ? (float)vi : __int_as_float(vi);

    int ncx = (int)((W + 127.0f) * 0.0078125f);
    int ncy = (int)((H + 127.0f) * 0.0078125f);
    bool useCells = (G <= MAXG) && (ncx >= 1) && (ncy >= 1) && (ncx * ncy <= NCELLMAX);

    for (int i = tid; i < G && i < MAXG; i += BM) {
        float4 g = gt[i];
        sgtb[i] = g;
        sga[i]  = (g.z - g.x) * (g.w - g.y);
    }
    if (tid < NCELLMAX) scnt[tid] = 0;
    if (tid == 0) soverflow = 0;
    __syncthreads();

    if (useCells && tid < G) {
        float4 g = sgtb[tid];
        int cx0 = max(0, min((int)(g.x * 0.0078125f), ncx - 1));
        int cx1 = max(0, min((int)(g.z * 0.0078125f), ncx - 1));
        int cy0 = max(0, min((int)(g.y * 0.0078125f), ncy - 1));
        int cy1 = max(0, min((int)(g.w * 0.0078125f), ncy - 1));
        for (int cy = cy0; cy <= cy1; cy++)
            for (int cx = cx0; cx <= cx1; cx++) {
                int cell = cy * ncx + cx;
                int pos = atomicAdd(&scnt[cell], 1);
                if (pos < CELLCAP) slist[cell * CELLCAP + pos] = (unsigned char)tid;
                else soverflow = 1;
            }
    }
    __syncthreads();

    int n = n0 + tid;
    if (n >= N) return;

    float4 p = prop[n];
    float pw = p.z - p.x, ph = p.w - p.y;
    float pcx = p.x + 0.5f * pw, pcy = p.y + 0.5f * ph;
    float parea = pw * ph;

    #define IOU_STEP(gg, nn, dd, ii)                                   \
        {   float4 gb = sgtb[(gg)];                                    \
            float lx = fmaxf(gb.x, p.x);                               \
            float ly = fmaxf(gb.y, p.y);                               \
            float rx = fminf(gb.z, p.z);                               \
            float ry = fminf(gb.w, p.w);                               \
            float iw = fmaxf(rx - lx, 0.f), ihh = fmaxf(ry - ly, 0.f); \
            float inter = iw * ihh;                                    \
            float den = sga[(gg)] + parea - inter;                     \
            if (inter * (dd) > (nn) * den) { (nn) = inter; (dd) = den; (ii) = (gg); } }
    int bg = 0;
    if (useCells && !soverflow) {
        float bnum = 0.f, bden = 1.f;
        int pcx0 = max(0, min((int)(p.x * 0.0078125f), ncx - 1));
        int pcx1 = max(0, min((int)(p.z * 0.0078125f), ncx - 1));
        int pcy0 = max(0, min((int)(p.y * 0.0078125f), ncy - 1));
        int pcy1 = max(0, min((int)(p.w * 0.0078125f), ncy - 1));
        for (int cy = pcy0; cy <= pcy1; cy++)
            for (int cx = pcx0; cx <= pcx1; cx++) {
                int cell = cy * ncx + cx;
                int cnt = min(scnt[cell], CELLCAP);
                const unsigned char* lp = slist + cell * CELLCAP;
                for (int k2 = 0; k2 < cnt; k2++) {
                    int g = lp[k2];
                    IOU_STEP(g, bnum, bden, bg);
                }
            }
    } else {
        float bnum = -1.f, bden = 1.f;
        for (int g = 0; g < G; g++) IOU_STEP(g, bnum, bden, bg);
    }
    #undef IOU_STEP

    float4 gb = sgtb[bg];
    float gw = gb.z - gb.x, gh = gb.w - gb.y;
    float gcx = gb.x + 0.5f * gw, gcy = gb.y + 0.5f * gh;
    float4 rt;
    rt.x = __fdividef(gcx - pcx, pw);
    rt.y = __fdividef(gcy - pcy, ph);
    rt.z = __logf(__fdividef(gw, pw));
    rt.w = __logf(__fdividef(gh, ph));
    out[TOPK + n] = rt;
}

// =================== K2: findbin ====
__global__ void __launch_bounds__(1024) findbin_kernel() {
    __shared__ int csum[1024];
    __shared__ int wsum[32];
    __shared__ int s_chunk, s_excl;
    int tid = threadIdx.x;
    int w = tid >> 5, lane = tid & 31;

    for (int c = w; c < 1024; c += 32) {
        int base = HBINS - (c + 1) * 64;
        int s = g_hist[base + lane] + g_hist[base + 32 + lane];
        s = __reduce_add_sync(0xFFFFFFFFu, s);
        if (lane == 0) csum[c] = s;
    }
    __syncthreads();

    int v = csum[tid];
    int x = v;
    #pragma unroll
    for (int o = 1; o < 32; o <<= 1) {
        int y = __shfl_up_sync(0xFFFFFFFFu, x, o);
        if (lane >= o) x += y;
    }
    if (lane == 31) wsum[w] = x;
    __syncthreads();
    if (w == 0) {
        int s = wsum[lane];
        #pragma unroll
        for (int o = 1; o < 32; o <<= 1) {
            int y = __shfl_up_sync(0xFFFFFFFFu, s, o);
            if (lane >= o) s += y;
        }
        wsum[lane] = s;
    }
    __syncthreads();
    int incl = x + ((w > 0) ? wsum[w - 1] : 0);
    int excl = incl - v;
    if (excl < TOPK && incl >= TOPK) { s_chunk = tid; s_excl = excl; }
    __syncthreads();

    if (w == 0) {
        int chunk = s_chunk, be = s_excl;
        int base = HBINS - (chunk + 1) * 64;
        int x0 = g_hist[base + 63 - lane];
        int x1 = g_hist[base + 31 - lane];
        int s0 = x0;
        #pragma unroll
        for (int o = 1; o < 32; o <<= 1) {
            int y = __shfl_up_sync(0xFFFFFFFFu, s0, o);
            if (lane >= o) s0 += y;
        }
        int t0 = __shfl_sync(0xFFFFFFFFu, s0, 31);
        int s1 = x1;
        #pragma unroll
        for (int o = 1; o < 32; o <<= 1) {
            int y = __shfl_up_sync(0xFFFFFFFFu, s1, o);
            if (lane >= o) s1 += y;
        }
        int incl0 = be + s0, excl0 = incl0 - x0;
        if (excl0 < TOPK && incl0 >= TOPK) g_binB = base + 63 - lane;
        int incl1 = be + t0 + s1, excl1 = incl1 - x1;
        if (excl1 < TOPK && incl1 >= TOPK) g_binB = base + 31 - lane;
    }
}

// =================== K3: compact + hist re-zero ============
__global__ void __launch_bounds__(256) compact_kernel(int N) {
    int gid = blockIdx.x * 256 + threadIdx.x;
    if (gid < N) {
        unsigned bits = __float_as_uint(g_score[gid]);
        if ((int)(bits >> 16) >= g_binB) {
            int pos = atomicAdd(&g_candcount, 1);
            if (pos < CAP)
                g_cand[pos] = ((ull)bits << 32) | (unsigned)(~gid);
        }
    }
    if (gid < HBINS) g_hist[gid] = 0;      // parallel re-zero for next replay
}

// bitonic shfl pass on a register-resident element (j <= 16, intra-warp)
__device__ __forceinline__ void shfl_pass(ull& v, int i, int j, int k) {
    ull wv = __shfl_xor_sync(0xFFFFFFFFu, v, j);
    bool desc  = ((i & k) == 0);
    bool lower = ((i & j) == 0);
    bool takeMax = (desc == lower);
    bool gt = v > wv;
    v = (takeMax == gt) ? v : wv;
}

__device__ __forceinline__ void store_topidx(int pos, ull key) {
    unsigned n = ~(unsigned)(key & 0xFFFFFFFFULL);
    if (n >= MAXN) n = 0;                  // defensive: never OOB
    g_topidx[pos] = (int)n;
}

// =================== K4: bitonic sort (regs+shfl inner passes) ============
__global__ void __launch_bounds__(1024) sort_kernel() {
    extern __shared__ ull sk[];
    int t = threadIdx.x;
    int M = g_candcount; if (M > CAP) M = CAP;
    __syncthreads();                       // ALL threads read candcount first
    if (t == 0) g_candcount = 0;           // then reset for next replay
    int P = 2048;
    while (P < M) P <<= 1;

    if (P == 2048) {
        const int i0 = t, i1 = t + 1024;
        ull v0 = (i0 < M) ? g_cand[i0] : 0ULL;
        ull v1 = (i1 < M) ? g_cand[i1] : 0ULL;
        #pragma unroll
        for (int k = 2; k <= 32; k <<= 1)
            #pragma unroll
            for (int j = k >> 1; j > 0; j >>= 1) {
                shfl_pass(v0, i0, j, k);
                shfl_pass(v1, i1, j, k);
            }
        for (int k = 64; k <= 2048; k <<= 1) {
            sk[i0] = v0; sk[i1] = v1;
            __syncthreads();
            for (int j = k >> 1; j >= 32; j >>= 1) {
                #pragma unroll
                for (int e = 0; e < 2; e++) {
                    int i = t + (e << 10);
                    int l = i ^ j;
                    if (l > i) {
                        bool desc = ((i & k) == 0);
                        ull a = sk[i], b = sk[l];
                        if (desc ? (a < b) : (a > b)) { sk[i] = b; sk[l] = a; }
                    }
                }
                __syncthreads();
            }
            v0 = sk[i0]; v1 = sk[i1];
            #pragma unroll
            for (int j = 16; j > 0; j >>= 1) {
                shfl_pass(v0, i0, j, k);
                shfl_pass(v1, i1, j, k);
            }
        }
        if (i0 < TOPK) store_topidx(i0, v0);
        if (i1 < TOPK) store_topidx(i1, v1);
    } else {
        int epw = P >> 10;
        for (int e = 0; e < epw; e++) {
            int i = t + (e << 10);
            sk[i] = (i < M) ? g_cand[i] : 0ULL;
        }
        __syncthreads();
        for (int k = 2; k <= P; k <<= 1)
            for (int j = k >> 1; j > 0; j >>= 1) {
                for (int e = 0; e < epw; e++) {
                    int i = t + (e << 10);
                    int l = i ^ j;
                    if (l > i) {
                        bool desc = ((i & k) == 0);
                        ull a = sk[i], b = sk[l];
                        if (desc ? (a < b) : (a > b)) { sk[i] = b; sk[l] = a; }
                    }
                }
                __syncthreads();
            }
        for (int i = t; i < TOPK; i += 1024) store_topidx(i, sk[i]);
    }
}

// =================== K5: decode only the 2000 winners ======================
__global__ void __launch_bounds__(256) decode_kernel(
        const float4* __restrict__ prop,
        const float4* __restrict__ btp,
        const int* __restrict__ ihp,
        const int* __restrict__ iwp,
        int C)
{
    int i = blockIdx.x * 256 + threadIdx.x;
    if (i >= TOPK) return;
    int vi = ihp[0];
    float H = (vi > 0 && vi < 1000000) ? (float)vi : __int_as_float(vi);
    vi = iwp[0];
    float W = (vi > 0 && vi < 1000000) ? (float)vi : __int_as_float(vi);

    int n = g_topidx[i];
    int bc = (int)g_cls[n];
    float4 p = prop[n];
    float pw = p.z - p.x, ph = p.w - p.y;
    float pcx = p.x + 0.5f * pw, pcy = p.y + 0.5f * ph;

    float4 t = btp[(size_t)n * C + bc];
    float dcx = t.x * pw + pcx;
    float dcy = t.y * ph + pcy;
    float dw  = __expf(t.z) * pw;
    float dh  = __expf(t.w) * ph;
    float4 box;
    box.x = fminf(fmaxf(dcx - 0.5f * dw, 0.f), W);
    box.y = fminf(fmaxf(dcy - 0.5f * dh, 0.f), H);
    box.z = fminf(fmaxf(dcx + 0.5f * dw, 0.f), W);
    box.w = fminf(fmaxf(dcy + 0.5f * dh, 0.f), H);
    g_topboxes[i] = box;
}

// =================== K6: NMS suppression bitmask (upper triangle only) =====
__global__ void __launch_bounds__(256) nms_mask_kernel() {
    __shared__ float4 sb[64];
    int cb  = blockIdx.x;
    int rby = blockIdx.y;
    if (cb * 64 + 63 < rby * 256) return;  // never consumed by the scan
    int t = threadIdx.x;
    int col0 = cb * 64;
    if (t < 64 && col0 + t < TOPK) sb[t] = g_topboxes[col0 + t];
    __syncthreads();
    int row = rby * 256 + t;
    if (row >= TOPK) return;
    float4 a = g_topboxes[row];
    float aarea = (a.z - a.x) * (a.w - a.y);
    ull bits = 0;
    int nj = min(64, TOPK - col0);
    for (int j = 0; j < nj; j++) {
        float4 b = sb[j];
        float lx = fmaxf(a.x, b.x), ly = fmaxf(a.y, b.y);
        float rx = fminf(a.z, b.z), ry = fminf(a.w, b.w);
        float iw = fmaxf(rx - lx, 0.f), ih = fmaxf(ry - ly, 0.f);
        float inter = iw * ih;
        float barea = (b.z - b.x) * (b.w - b.y);
        float iou = __fdividef(inter, aarea + barea - inter);
        if (iou > NMS_THR) bits |= (1ULL << j);   // NaN compares false
    }
    g_mask[row * CBLK + cb] = bits;
}

// =================== K7: greedy scan + final write ========================
__global__ void __launch_bounds__(256) nms_final_kernel(float* __restrict__ out) {
    __shared__ ull skeep[CBLK];
    int t = threadIdx.x;
    if (t < 32) {
        ull rem = 0;
        ull cur_sup = 0;
        ull kw = 0;
        ull bit = 1;
        const int D = 16;
        ull buf[D];
        #pragma unroll
        for (int k = 0; k < D; k++) buf[k] = g_mask[k * CBLK + t];
        ull m0 = __shfl_sync(0xFFFFFFFFu, buf[0], 0);
        ull m1 = __shfl_sync(0xFFFFFFFFu, buf[1], 0);
        ull m2 = __shfl_sync(0xFFFFFFFFu, buf[2], 0);
        ull m3 = __shfl_sync(0xFFFFFFFFu, buf[3], 0);
        for (int i = 0; i < TOPK; i++) {
            ull cur = buf[i & (D - 1)];
            ull mn = 0;
            if (i + 4 < TOPK)
                mn = __shfl_sync(0xFFFFFFFFu, buf[(i + 4) & (D - 1)], (i + 4) >> 6);
            if (i + D < TOPK) buf[i & (D - 1)] = g_mask[(i + D) * CBLK + t];

            bool keep = (cur_sup & bit) == 0ULL;
            if (keep) { cur_sup |= m0; kw |= bit; }
            rem |= keep ? cur : 0ULL;

            if ((i & 63) == 63) {
                if (t == 0) skeep[i >> 6] = kw;
                kw = 0; bit = 1;
                cur_sup = __shfl_sync(0xFFFFFFFFu, rem, (i + 1) >> 6);
            } else {
                bit <<= 1;
            }
            m0 = m1; m1 = m2; m2 = m3; m3 = mn;
        }
        if (t == 0) skeep[(TOPK - 1) >> 6] = kw;
    }
    __syncthreads();
    const float* tb = (const float*)g_topboxes;
    for (int idx = t; idx < TOPK * 4; idx += 256) {
        int r = idx >> 2;
        float k = ((skeep[r >> 6] >> (r & 63)) & 1ULL) ? 1.0f : 0.0f;
        out[idx] = tb[idx] * k;
    }
}

// ---------------- launcher: forked graph ----------------
extern "C" void kernel_launch(void* const* d_in, const int* in_sizes, int n_in,
                              void* d_out, int out_size)
{
    const float4* prop = (const float4*)d_in[0];
    const float4* btp  = (const float4*)d_in[1];
    const float*  cls  = (const float*)d_in[2];
    const float4* gt   = (const float4*)d_in[3];
    const int*    ih   = (const int*)d_in[4];
    const int*    iw   = (const int*)d_in[5];
    float*        out  = (float*)d_out;

    int N = in_sizes[0] / 4;
    int C = in_sizes[2] / N;
    int G = in_sizes[3] / 4;

    // one-time resources (first call is the uncaptured correctness run)
    static cudaStream_t sB = nullptr;
    static cudaEvent_t  evFork = nullptr, evJoin = nullptr;
    static int init_done = 0;
    if (!init_done) {
        cudaFuncSetAttribute(sort_kernel,
                             cudaFuncAttributeMaxDynamicSharedMemorySize,
                             CAP * (int)sizeof(ull));
        if (cudaStreamCreateWithFlags(&sB, cudaStreamNonBlocking) != cudaSuccess)
            sB = nullptr;
        if (cudaEventCreateWithFlags(&evFork, cudaEventDisableTiming) != cudaSuccess)
            evFork = nullptr;
        if (cudaEventCreateWithFlags(&evJoin, cudaEventDisableTiming) != cudaSuccess)
            evJoin = nullptr;
        init_done = 1;
    }
    bool fork = (sB && evFork && evJoin);

    int gridP = (N + BM - 1) / BM;
    int smem_score = BM * 21 * (int)sizeof(float);

    // ---- branch B: reg_targets (independent of everything below) ----
    if (fork) {
        cudaEventRecord(evFork, 0);
        cudaStreamWaitEvent(sB, evFork, 0);
        regtarget_kernel<<<gridP, BM, 0, sB>>>(prop, gt, ih, iw, (float4*)out, N, G);
        cudaEventRecord(evJoin, sB);
    } else {
        regtarget_kernel<<<gridP, BM>>>(prop, gt, ih, iw, (float4*)out, N, G);
    }

    // ---- branch A: score -> topk -> nms ----
    score_kernel<<<gridP, BM, smem_score>>>(cls, N, C);
    findbin_kernel<<<1, 1024>>>();
    compact_kernel<<<(N + 255) / 256, 256>>>(N);
    sort_kernel<<<1, 1024, CAP * sizeof(ull)>>>();
    decode_kernel<<<(TOPK + 255) / 256, 256>>>(prop, btp, ih, iw, C);

    dim3 grid((TOPK + 63) / 64, (TOPK + 255) / 256);
    nms_mask_kernel<<<grid, 256>>>();
    nms_final_kernel<<<1, 256>>>(out);

    // ---- join branch B before the graph ends ----
    if (fork) cudaStreamWaitEvent(0, evJoin, 0);
}

// round 11
// speedup vs baseline: 1.0085x; 1.0085x over previous
#include <cuda_runtime.h>
#include <cstdint>

#define TOPK      2000
#define NMS_THR   0.5f
#define MAXN      200000
#define MAXG      128
#define HBINS     65536
#define CAP       8192
#define CBLK      32          // ceil(TOPK/64)
#define BM        256         // proposals per block
#define NCELLMAX  128         // max grid cells (11x7=77 typical)
#define CELLCAP   24          // max GT entries per cell

typedef unsigned long long ull;

// ---------------- scratch (no allocation allowed) ----------------
__device__ float               g_score[MAXN];
__device__ unsigned char       g_cls[MAXN];
__device__ __align__(16) int   g_hist[HBINS];    // zero at load; re-zeroed in compact
__device__ int                 g_candcount;      // zero at load; reset in sort
__device__ int                 g_binB;
__device__ ull                 g_cand[CAP];
__device__ float4              g_topboxes[TOPK];
__device__ ull                 g_mask[TOPK * CBLK];

// =================== K1: scores only =====================
__global__ void __launch_bounds__(BM) score_kernel(
        const float*  __restrict__ cls,
        int N, int C)
{
    extern __shared__ float scls[];       // BM*21 floats (stride 21 -> conflict-free)
    int tid = threadIdx.x;
    int n0  = blockIdx.x * BM;
    int rows = min(BM, N - n0);
    if (rows <= 0) return;

    const float* cbase = cls + (size_t)n0 * C;
    if (C == 21 && rows == BM) {
        // BM*21/4 = 1344 float4; base offset blk*21504B is 16B-aligned
        const float4* c4 = (const float4*)cbase;
        float4* s4 = (float4*)scls;
        #pragma unroll
        for (int e = 0; e < 5; e++)
            s4[tid + e * BM] = c4[tid + e * BM];
        {   int idx = tid + 5 * BM;        // remainder 64
            if (idx < BM * 21 / 4) s4[idx] = c4[idx];
        }
    } else {
        int total = rows * C;
        for (int idx = tid; idx < total; idx += BM) {
            int r = idx / C;
            scls[r * 21 + (idx - r * C)] = cbase[idx];
        }
    }
    __syncthreads();

    int n = n0 + tid;
    if (n >= N) return;

    const float* cr = scls + tid * 21;
    float m = cr[0], bl = -1e30f; int bc = 1;
    #pragma unroll
    for (int c = 1; c < 21; c++) {
        float v = cr[c];
        m = fmaxf(m, v);
        if (v > bl) { bl = v; bc = c; }
    }
    float Z = 0.f;
    #pragma unroll
    for (int c = 0; c < 21; c++) Z += __expf(cr[c] - m);
    float score = __fdividef(__expf(bl - m), Z);

    g_score[n] = score;
    g_cls[n]   = (unsigned char)bc;
    atomicAdd(&g_hist[__float_as_uint(score) >> 16], 1);
}

// =================== K2: reg_targets ==============
__global__ void __launch_bounds__(BM) regtarget_kernel(
        const float4* __restrict__ prop,
        const float4* __restrict__ gt,
        const int* __restrict__ ihp,
        const int* __restrict__ iwp,
        float4* __restrict__ out,         // rows TOPK..TOPK+N
        int N, int G)
{
    __shared__ float4        sgtb[MAXG];
    __shared__ float         sga[MAXG];
    __shared__ int           scnt[NCELLMAX];
    __shared__ unsigned char slist[NCELLMAX * CELLCAP];
    __shared__ int           soverflow;

    int tid = threadIdx.x;
    int n0  = blockIdx.x * BM;

    int vi = ihp[0];
    float H = (vi > 0 && vi < 1000000) ? (float)vi : __int_as_float(vi);
    vi = iwp[0];
    float W = (vi > 0 && vi < 1000000) ? (float)vi : __int_as_float(vi);

    int ncx = (int)((W + 127.0f) * 0.0078125f);
    int ncy = (int)((H + 127.0f) * 0.0078125f);
    bool useCells = (G <= MAXG) && (ncx >= 1) && (ncy >= 1) && (ncx * ncy <= NCELLMAX);

    for (int i = tid; i < G && i < MAXG; i += BM) {
        float4 g = gt[i];
        sgtb[i] = g;
        sga[i]  = (g.z - g.x) * (g.w - g.y);
    }
    if (tid < NCELLMAX) scnt[tid] = 0;
    if (tid == 0) soverflow = 0;
    __syncthreads();

    if (useCells && tid < G) {
        float4 g = sgtb[tid];
        int cx0 = max(0, min((int)(g.x * 0.0078125f), ncx - 1));
        int cx1 = max(0, min((int)(g.z * 0.0078125f), ncx - 1));
        int cy0 = max(0, min((int)(g.y * 0.0078125f), ncy - 1));
        int cy1 = max(0, min((int)(g.w * 0.0078125f), ncy - 1));
        for (int cy = cy0; cy <= cy1; cy++)
            for (int cx = cx0; cx <= cx1; cx++) {
                int cell = cy * ncx + cx;
                int pos = atomicAdd(&scnt[cell], 1);
                if (pos < CELLCAP) slist[cell * CELLCAP + pos] = (unsigned char)tid;
                else soverflow = 1;
            }
    }
    __syncthreads();

    int n = n0 + tid;
    if (n >= N) return;

    float4 p = prop[n];
    float pw = p.z - p.x, ph = p.w - p.y;
    float pcx = p.x + 0.5f * pw, pcy = p.y + 0.5f * ph;
    float parea = pw * ph;

    #define IOU_STEP(gg, nn, dd, ii)                                   \
        {   float4 gb = sgtb[(gg)];                                    \
            float lx = fmaxf(gb.x, p.x);                               \
            float ly = fmaxf(gb.y, p.y);                               \
            float rx = fminf(gb.z, p.z);                               \
            float ry = fminf(gb.w, p.w);                               \
            float iw = fmaxf(rx - lx, 0.f), ihh = fmaxf(ry - ly, 0.f); \
            float inter = iw * ihh;                                    \
            float den = sga[(gg)] + parea - inter;                     \
            if (inter * (dd) > (nn) * den) { (nn) = inter; (dd) = den; (ii) = (gg); } }
    int bg = 0;
    if (useCells && !soverflow) {
        float bnum = 0.f, bden = 1.f;
        int pcx0 = max(0, min((int)(p.x * 0.0078125f), ncx - 1));
        int pcx1 = max(0, min((int)(p.z * 0.0078125f), ncx - 1));
        int pcy0 = max(0, min((int)(p.y * 0.0078125f), ncy - 1));
        int pcy1 = max(0, min((int)(p.w * 0.0078125f), ncy - 1));
        for (int cy = pcy0; cy <= pcy1; cy++)
            for (int cx = pcx0; cx <= pcx1; cx++) {
                int cell = cy * ncx + cx;
                int cnt = min(scnt[cell], CELLCAP);
                const unsigned char* lp = slist + cell * CELLCAP;
                for (int k2 = 0; k2 < cnt; k2++) {
                    int g = lp[k2];
                    IOU_STEP(g, bnum, bden, bg);
                }
            }
    } else {
        float bnum = -1.f, bden = 1.f;
        for (int g = 0; g < G; g++) IOU_STEP(g, bnum, bden, bg);
    }
    #undef IOU_STEP

    float4 gb = sgtb[bg];
    float gw = gb.z - gb.x, gh = gb.w - gb.y;
    float gcx = gb.x + 0.5f * gw, gcy = gb.y + 0.5f * gh;
    float4 rt;
    rt.x = __fdividef(gcx - pcx, pw);
    rt.y = __fdividef(gcy - pcy, ph);
    rt.z = __logf(__fdividef(gw, pw));
    rt.w = __logf(__fdividef(gh, ph));
    out[TOPK + n] = rt;
}

// =================== K3: findbin ====
__global__ void __launch_bounds__(1024) findbin_kernel() {
    __shared__ int csum[1024];
    __shared__ int wsum[32];
    __shared__ int s_chunk, s_excl;
    int tid = threadIdx.x;
    int w = tid >> 5, lane = tid & 31;

    for (int c = w; c < 1024; c += 32) {
        int base = HBINS - (c + 1) * 64;
        int s = g_hist[base + lane] + g_hist[base + 32 + lane];
        s = __reduce_add_sync(0xFFFFFFFFu, s);
        if (lane == 0) csum[c] = s;
    }
    __syncthreads();

    int v = csum[tid];
    int x = v;
    #pragma unroll
    for (int o = 1; o < 32; o <<= 1) {
        int y = __shfl_up_sync(0xFFFFFFFFu, x, o);
        if (lane >= o) x += y;
    }
    if (lane == 31) wsum[w] = x;
    __syncthreads();
    if (w == 0) {
        int s = wsum[lane];
        #pragma unroll
        for (int o = 1; o < 32; o <<= 1) {
            int y = __shfl_up_sync(0xFFFFFFFFu, s, o);
            if (lane >= o) s += y;
        }
        wsum[lane] = s;
    }
    __syncthreads();
    int incl = x + ((w > 0) ? wsum[w - 1] : 0);
    int excl = incl - v;
    if (excl < TOPK && incl >= TOPK) { s_chunk = tid; s_excl = excl; }
    __syncthreads();

    if (w == 0) {
        int chunk = s_chunk, be = s_excl;
        int base = HBINS - (chunk + 1) * 64;
        int x0 = g_hist[base + 63 - lane];
        int x1 = g_hist[base + 31 - lane];
        int s0 = x0;
        #pragma unroll
        for (int o = 1; o < 32; o <<= 1) {
            int y = __shfl_up_sync(0xFFFFFFFFu, s0, o);
            if (lane >= o) s0 += y;
        }
        int t0 = __shfl_sync(0xFFFFFFFFu, s0, 31);
        int s1 = x1;
        #pragma unroll
        for (int o = 1; o < 32; o <<= 1) {
            int y = __shfl_up_sync(0xFFFFFFFFu, s1, o);
            if (lane >= o) s1 += y;
        }
        int incl0 = be + s0, excl0 = incl0 - x0;
        if (excl0 < TOPK && incl0 >= TOPK) g_binB = base + 63 - lane;
        int incl1 = be + t0 + s1, excl1 = incl1 - x1;
        if (excl1 < TOPK && incl1 >= TOPK) g_binB = base + 31 - lane;
    }
}

// =================== K4: compact + hist re-zero ============
__global__ void __launch_bounds__(256) compact_kernel(int N) {
    int gid = blockIdx.x * 256 + threadIdx.x;
    if (gid < N) {
        unsigned bits = __float_as_uint(g_score[gid]);
        if ((int)(bits >> 16) >= g_binB) {
            int pos = atomicAdd(&g_candcount, 1);
            if (pos < CAP)
                g_cand[pos] = ((ull)bits << 32) | (unsigned)(~gid);
        }
    }
    if (gid < HBINS) g_hist[gid] = 0;      // parallel re-zero for next replay
}

// bitonic shfl pass on a register-resident element (j <= 16, intra-warp)
__device__ __forceinline__ void shfl_pass(ull& v, int i, int j, int k) {
    ull wv = __shfl_xor_sync(0xFFFFFFFFu, v, j);
    bool desc  = ((i & k) == 0);
    bool lower = ((i & j) == 0);
    bool takeMax = (desc == lower);
    bool gt = v > wv;
    v = (takeMax == gt) ? v : wv;
}

// decode one winner's box (same arithmetic as reference path)
__device__ __forceinline__ void decode_one(
        int pos, ull key,
        const float4* __restrict__ prop,
        const float4* __restrict__ btp,
        int C, float W, float H)
{
    unsigned n = ~(unsigned)(key & 0xFFFFFFFFULL);
    if (n >= MAXN) n = 0;                  // defensive: never OOB
    int bc = (int)g_cls[n];
    float4 p = prop[n];
    float pw = p.z - p.x, ph = p.w - p.y;
    float pcx = p.x + 0.5f * pw, pcy = p.y + 0.5f * ph;
    float4 t = btp[(size_t)n * C + bc];
    float dcx = t.x * pw + pcx;
    float dcy = t.y * ph + pcy;
    float dw  = __expf(t.z) * pw;
    float dh  = __expf(t.w) * ph;
    float4 box;
    box.x = fminf(fmaxf(dcx - 0.5f * dw, 0.f), W);
    box.y = fminf(fmaxf(dcy - 0.5f * dh, 0.f), H);
    box.z = fminf(fmaxf(dcx + 0.5f * dw, 0.f), W);
    box.w = fminf(fmaxf(dcy + 0.5f * dh, 0.f), H);
    g_topboxes[pos] = box;
}

// =================== K5: bitonic sort + fused winner decode ===============
__global__ void __launch_bounds__(1024) sort_kernel(
        const float4* __restrict__ prop,
        const float4* __restrict__ btp,
        const int* __restrict__ ihp,
        const int* __restrict__ iwp,
        int C)
{
    extern __shared__ ull sk[];
    int t = threadIdx.x;
    int M = g_candcount; if (M > CAP) M = CAP;
    __syncthreads();                       // ALL threads read candcount first
    if (t == 0) g_candcount = 0;           // then reset for next replay

    int vi = ihp[0];
    float H = (vi > 0 && vi < 1000000) ? (float)vi : __int_as_float(vi);
    vi = iwp[0];
    float W = (vi > 0 && vi < 1000000) ? (float)vi : __int_as_float(vi);

    int P = 2048;
    while (P < M) P <<= 1;

    if (P == 2048) {
        const int i0 = t, i1 = t + 1024;
        ull v0 = (i0 < M) ? g_cand[i0] : 0ULL;
        ull v1 = (i1 < M) ? g_cand[i1] : 0ULL;
        #pragma unroll
        for (int k = 2; k <= 32; k <<= 1)
            #pragma unroll
            for (int j = k >> 1; j > 0; j >>= 1) {
                shfl_pass(v0, i0, j, k);
                shfl_pass(v1, i1, j, k);
            }
        for (int k = 64; k <= 2048; k <<= 1) {
            sk[i0] = v0; sk[i1] = v1;
            __syncthreads();
            for (int j = k >> 1; j >= 32; j >>= 1) {
                #pragma unroll
                for (int e = 0; e < 2; e++) {
                    int i = t + (e << 10);
                    int l = i ^ j;
                    if (l > i) {
                        bool desc = ((i & k) == 0);
                        ull a = sk[i], b = sk[l];
                        if (desc ? (a < b) : (a > b)) { sk[i] = b; sk[l] = a; }
                    }
                }
                __syncthreads();
            }
            v0 = sk[i0]; v1 = sk[i1];
            #pragma unroll
            for (int j = 16; j > 0; j >>= 1) {
                shfl_pass(v0, i0, j, k);
                shfl_pass(v1, i1, j, k);
            }
        }
        if (i0 < TOPK) decode_one(i0, v0, prop, btp, C, W, H);
        if (i1 < TOPK) decode_one(i1, v1, prop, btp, C, W, H);
    } else {
        int epw = P >> 10;
        for (int e = 0; e < epw; e++) {
            int i = t + (e << 10);
            sk[i] = (i < M) ? g_cand[i] : 0ULL;
        }
        __syncthreads();
        for (int k = 2; k <= P; k <<= 1)
            for (int j = k >> 1; j > 0; j >>= 1) {
                for (int e = 0; e < epw; e++) {
                    int i = t + (e << 10);
                    int l = i ^ j;
                    if (l > i) {
                        bool desc = ((i & k) == 0);
                        ull a = sk[i], b = sk[l];
                        if (desc ? (a < b) : (a > b)) { sk[i] = b; sk[l] = a; }
                    }
                }
                __syncthreads();
            }
        for (int i = t; i < TOPK; i += 1024)
            decode_one(i, sk[i], prop, btp, C, W, H);
    }
}

// =================== K6: NMS suppression bitmask (upper triangle only) =====
__global__ void __launch_bounds__(256) nms_mask_kernel() {
    __shared__ float4 sb[64];
    int cb  = blockIdx.x;
    int rby = blockIdx.y;
    if (cb * 64 + 63 < rby * 256) return;  // never consumed by the scan
    int t = threadIdx.x;
    int col0 = cb * 64;
    if (t < 64 && col0 + t < TOPK) sb[t] = g_topboxes[col0 + t];
    __syncthreads();
    int row = rby * 256 + t;
    if (row >= TOPK) return;
    float4 a = g_topboxes[row];
    float aarea = (a.z - a.x) * (a.w - a.y);
    ull bits = 0;
    int nj = min(64, TOPK - col0);
    for (int j = 0; j < nj; j++) {
        float4 b = sb[j];
        float lx = fmaxf(a.x, b.x), ly = fmaxf(a.y, b.y);
        float rx = fminf(a.z, b.z), ry = fminf(a.w, b.w);
        float iw = fmaxf(rx - lx, 0.f), ih = fmaxf(ry - ly, 0.f);
        float inter = iw * ih;
        float barea = (b.z - b.x) * (b.w - b.y);
        float iou = __fdividef(inter, aarea + barea - inter);
        if (iou > NMS_THR) bits |= (1ULL << j);   // NaN compares false
    }
    g_mask[row * CBLK + cb] = bits;
}

// =================== K7: greedy scan + final write ========================
__global__ void __launch_bounds__(256) nms_final_kernel(float* __restrict__ out) {
    __shared__ ull skeep[CBLK];
    int t = threadIdx.x;
    if (t < 32) {
        ull rem = 0;
        ull cur_sup = 0;
        ull kw = 0;
        ull bit = 1;
        const int D = 16;
        ull buf[D];
        #pragma unroll
        for (int k = 0; k < D; k++) buf[k] = g_mask[k * CBLK + t];
        ull m0 = __shfl_sync(0xFFFFFFFFu, buf[0], 0);
        ull m1 = __shfl_sync(0xFFFFFFFFu, buf[1], 0);
        ull m2 = __shfl_sync(0xFFFFFFFFu, buf[2], 0);
        ull m3 = __shfl_sync(0xFFFFFFFFu, buf[3], 0);
        for (int i = 0; i < TOPK; i++) {
            ull cur = buf[i & (D - 1)];
            ull mn = 0;
            if (i + 4 < TOPK)
                mn = __shfl_sync(0xFFFFFFFFu, buf[(i + 4) & (D - 1)], (i + 4) >> 6);
            if (i + D < TOPK) buf[i & (D - 1)] = g_mask[(i + D) * CBLK + t];

            bool keep = (cur_sup & bit) == 0ULL;
            if (keep) { cur_sup |= m0; kw |= bit; }
            rem |= keep ? cur : 0ULL;

            if ((i & 63) == 63) {
                if (t == 0) skeep[i >> 6] = kw;
                kw = 0; bit = 1;
                cur_sup = __shfl_sync(0xFFFFFFFFu, rem, (i + 1) >> 6);
            } else {
                bit <<= 1;
            }
            m0 = m1; m1 = m2; m2 = m3; m3 = mn;
        }
        if (t == 0) skeep[(TOPK - 1) >> 6] = kw;
    }
    __syncthreads();
    const float* tb = (const float*)g_topboxes;
    for (int idx = t; idx < TOPK * 4; idx += 256) {
        int r = idx >> 2;
        float k = ((skeep[r >> 6] >> (r & 63)) & 1ULL) ? 1.0f : 0.0f;
        out[idx] = tb[idx] * k;
    }
}

// ---------------- launcher: 6 graph nodes ----------------
extern "C" void kernel_launch(void* const* d_in, const int* in_sizes, int n_in,
                              void* d_out, int out_size)
{
    const float4* prop = (const float4*)d_in[0];
    const float4* btp  = (const float4*)d_in[1];
    const float*  cls  = (const float*)d_in[2];
    const float4* gt   = (const float4*)d_in[3];
    const int*    ih   = (const int*)d_in[4];
    const int*    iw   = (const int*)d_in[5];
    float*        out  = (float*)d_out;

    int N = in_sizes[0] / 4;
    int C = in_sizes[2] / N;
    int G = in_sizes[3] / 4;

    static int init_done = 0;
    if (!init_done) {
        cudaFuncSetAttribute(sort_kernel,
                             cudaFuncAttributeMaxDynamicSharedMemorySize,
                             CAP * (int)sizeof(ull));
        init_done = 1;
    }

    int gridP = (N + BM - 1) / BM;
    int smem_score = BM * 21 * (int)sizeof(float);

    score_kernel<<<gridP, BM, smem_score>>>(cls, N, C);
    regtarget_kernel<<<gridP, BM>>>(prop, gt, ih, iw, (float4*)out, N, G);
    findbin_kernel<<<1, 1024>>>();
    compact_kernel<<<(N + 255) / 256, 256>>>(N);
    sort_kernel<<<1, 1024, CAP * sizeof(ull)>>>(prop, btp, ih, iw, C);

    dim3 grid((TOPK + 63) / 64, (TOPK + 255) / 256);
    nms_mask_kernel<<<grid, 256>>>();
    nms_final_kernel<<<1, 256>>>(out);
}

// round 12
// speedup vs baseline: 1.4527x; 1.4404x over previous
#include <cuda_runtime.h>
#include <cstdint>

#define TOPK      2000
#define NMS_THR   0.5f
#define MAXN      200000
#define MAXG      128
#define HBINS     65536
#define CAP       8192
#define CBLK      32          // ceil(TOPK/64)
#define BM        256         // proposals per block
#define NCELLMAX  128         // max grid cells (11x7=77 typical)
#define CELLCAP   32          // max GT entries per expanded cell list

typedef unsigned long long ull;

// ---------------- scratch (no allocation allowed) ----------------
__device__ float               g_score[MAXN];
__device__ unsigned char       g_cls[MAXN];
__device__ __align__(16) int   g_hist[HBINS];    // zero at load; re-zeroed in compact
__device__ int                 g_candcount;      // zero at load; reset in sort
__device__ int                 g_binB;
__device__ ull                 g_cand[CAP];
__device__ float4              g_topboxes[TOPK];
__device__ ull                 g_mask[TOPK * CBLK];
__device__ ull                 g_diag[TOPK];     // diagonal mask word per row

// =================== K1: fused scores + reg_targets =======================
__global__ void __launch_bounds__(BM) main_kernel(
        const float4* __restrict__ prop,
        const float*  __restrict__ cls,
        const float4* __restrict__ gt,
        const int* __restrict__ ihp,
        const int* __restrict__ iwp,
        float4* __restrict__ out,         // rows TOPK..TOPK+N
        int N, int C, int G)
{
    __shared__ float4        sgtb[MAXG];
    __shared__ float         sga[MAXG];
    __shared__ int           scnt[NCELLMAX];
    __shared__ unsigned char slist[NCELLMAX * CELLCAP];   // 4096 B, uint-aligned
    __shared__ int           soverflow;
    extern __shared__ float  scls[];      // BM*21 floats (stride 21 -> conflict-free)

    int tid = threadIdx.x;
    int n0  = blockIdx.x * BM;

    int vi = ihp[0];
    float H = (vi > 0 && vi < 1000000) ? (float)vi : __int_as_float(vi);
    vi = iwp[0];
    float W = (vi > 0 && vi < 1000000) ? (float)vi : __int_as_float(vi);

    int ncx = (int)((W + 127.0f) * 0.0078125f);
    int ncy = (int)((H + 127.0f) * 0.0078125f);
    bool useCells = (G <= MAXG) && (ncx >= 1) && (ncy >= 1) && (ncx * ncy <= NCELLMAX);

    for (int i = tid; i < G && i < MAXG; i += BM) {
        float4 g = gt[i];
        sgtb[i] = g;
        sga[i]  = (g.z - g.x) * (g.w - g.y);
    }
    if (tid < NCELLMAX) scnt[tid] = 0;
    if (tid == 0) soverflow = 0;

    // stage cls rows (coalesced float4 reads when C==21 and full block)
    {
        int rows = min(BM, N - n0);
        if (rows > 0) {
            const float* cbase = cls + (size_t)n0 * C;
            if (C == 21 && rows == BM) {
                const float4* c4 = (const float4*)cbase;
                float4* s4 = (float4*)scls;
                #pragma unroll
                for (int e = 0; e < 5; e++)
                    s4[tid + e * BM] = c4[tid + e * BM];
                {   int idx = tid + 5 * BM;
                    if (idx < BM * 21 / 4) s4[idx] = c4[idx];
                }
            } else {
                int total = rows * C;
                for (int idx = tid; idx < total; idx += BM) {
                    int r = idx / C;
                    scls[r * 21 + (idx - r * C)] = cbase[idx];
                }
            }
        }
    }
    __syncthreads();

    // expanded insertion: GT g goes into every cell whose 2x2 probe block it
    // could intersect, i.e. cells [gx0-1 .. gx1] x [gy0-1 .. gy1]
    if (useCells && tid < G) {
        float4 g = sgtb[tid];
        int gx0 = max(0, min((int)(g.x * 0.0078125f) - 1, ncx - 1));
        int gx1 = max(0, min((int)(g.z * 0.0078125f),     ncx - 1));
        int gy0 = max(0, min((int)(g.y * 0.0078125f) - 1, ncy - 1));
        int gy1 = max(0, min((int)(g.w * 0.0078125f),     ncy - 1));
        for (int cy = gy0; cy <= gy1; cy++)
            for (int cx = gx0; cx <= gx1; cx++) {
                int cell = cy * ncx + cx;
                int pos = atomicAdd(&scnt[cell], 1);
                if (pos < CELLCAP) slist[cell * CELLCAP + pos] = (unsigned char)tid;
                else soverflow = 1;
            }
    }
    __syncthreads();

    int n = n0 + tid;
    if (n >= N) return;

    float4 p = prop[n];
    float pw = p.z - p.x, ph = p.w - p.y;
    float pcx = p.x + 0.5f * pw, pcy = p.y + 0.5f * ph;
    float parea = pw * ph;

    // softmax score + fg argmax (from shared)
    const float* cr = scls + tid * 21;
    float m = cr[0], bl = -1e30f; int bc = 1;
    #pragma unroll
    for (int c = 1; c < 21; c++) {
        float v = cr[c];
        m = fmaxf(m, v);
        if (v > bl) { bl = v; bc = c; }
    }
    float Z = 0.f;
    #pragma unroll
    for (int c = 0; c < 21; c++) Z += __expf(cr[c] - m);
    float score = __fdividef(__expf(bl - m), Z);

    g_score[n] = score;
    g_cls[n]   = (unsigned char)bc;
    atomicAdd(&g_hist[__float_as_uint(score) >> 16], 1);

    // best-IoU gt match
    #define IOU_STEP(gg, nn, dd, ii)                                   \
        {   float4 gb = sgtb[(gg)];                                    \
            float lx = fmaxf(gb.x, p.x);                               \
            float ly = fmaxf(gb.y, p.y);                               \
            float rx = fminf(gb.z, p.z);                               \
            float ry = fminf(gb.w, p.w);                               \
            float iw = fmaxf(rx - lx, 0.f), ihh = fmaxf(ry - ly, 0.f); \
            float inter = iw * ihh;                                    \
            float den = sga[(gg)] + parea - inter;                     \
            if (inter * (dd) > (nn) * den) { (nn) = inter; (dd) = den; (ii) = (gg); } }
    int bg = 0;
    if (useCells && !soverflow) {
        // single probe cell: top-left corner cell of the proposal. The
        // expanded insertion guarantees every GT with IoU>0 is in this list.
        float bnum = 0.f, bden = 1.f;
        int pcx0 = max(0, min((int)(p.x * 0.0078125f), ncx - 1));
        int pcy0 = max(0, min((int)(p.y * 0.0078125f), ncy - 1));
        int cell = pcy0 * ncx + pcx0;
        int cnt = min(scnt[cell], CELLCAP);
        // fetch the whole list upfront (8 independent LDS.32, pipelined)
        const unsigned* lw = (const unsigned*)(slist + cell * CELLCAP);
        unsigned u[CELLCAP / 4];
        #pragma unroll
        for (int w2 = 0; w2 < CELLCAP / 4; w2++) u[w2] = lw[w2];
        for (int k2 = 0; k2 < cnt; k2++) {
            int g = (u[k2 >> 2] >> ((k2 & 3) * 8)) & 255;
            IOU_STEP(g, bnum, bden, bg);
        }
    } else {
        float bnum = -1.f, bden = 1.f;
        for (int g = 0; g < G; g++) IOU_STEP(g, bnum, bden, bg);
    }
    #undef IOU_STEP

    float4 gb = sgtb[bg];
    float gw = gb.z - gb.x, gh = gb.w - gb.y;
    float gcx = gb.x + 0.5f * gw, gcy = gb.y + 0.5f * gh;
    float4 rt;
    rt.x = __fdividef(gcx - pcx, pw);
    rt.y = __fdividef(gcy - pcy, ph);
    rt.z = __logf(__fdividef(gw, pw));
    rt.w = __logf(__fdividef(gh, ph));
    out[TOPK + n] = rt;
}

// =================== K2: findbin ====
__global__ void __launch_bounds__(1024) findbin_kernel() {
    __shared__ int csum[1024];
    __shared__ int wsum[32];
    __shared__ int s_chunk, s_excl;
    int tid = threadIdx.x;
    int w = tid >> 5, lane = tid & 31;

    for (int c = w; c < 1024; c += 32) {
        int base = HBINS - (c + 1) * 64;
        int s = g_hist[base + lane] + g_hist[base + 32 + lane];
        s = __reduce_add_sync(0xFFFFFFFFu, s);
        if (lane == 0) csum[c] = s;
    }
    __syncthreads();

    int v = csum[tid];
    int x = v;
    #pragma unroll
    for (int o = 1; o < 32; o <<= 1) {
        int y = __shfl_up_sync(0xFFFFFFFFu, x, o);
        if (lane >= o) x += y;
    }
    if (lane == 31) wsum[w] = x;
    __syncthreads();
    if (w == 0) {
        int s = wsum[lane];
        #pragma unroll
        for (int o = 1; o < 32; o <<= 1) {
            int y = __shfl_up_sync(0xFFFFFFFFu, s, o);
            if (lane >= o) s += y;
        }
        wsum[lane] = s;
    }
    __syncthreads();
    int incl = x + ((w > 0) ? wsum[w - 1] : 0);
    int excl = incl - v;
    if (excl < TOPK && incl >= TOPK) { s_chunk = tid; s_excl = excl; }
    __syncthreads();

    if (w == 0) {
        int chunk = s_chunk, be = s_excl;
        int base = HBINS - (chunk + 1) * 64;
        int x0 = g_hist[base + 63 - lane];
        int x1 = g_hist[base + 31 - lane];
        int s0 = x0;
        #pragma unroll
        for (int o = 1; o < 32; o <<= 1) {
            int y = __shfl_up_sync(0xFFFFFFFFu, s0, o);
            if (lane >= o) s0 += y;
        }
        int t0 = __shfl_sync(0xFFFFFFFFu, s0, 31);
        int s1 = x1;
        #pragma unroll
        for (int o = 1; o < 32; o <<= 1) {
            int y = __shfl_up_sync(0xFFFFFFFFu, s1, o);
            if (lane >= o) s1 += y;
        }
        int incl0 = be + s0, excl0 = incl0 - x0;
        if (excl0 < TOPK && incl0 >= TOPK) g_binB = base + 63 - lane;
        int incl1 = be + t0 + s1, excl1 = incl1 - x1;
        if (excl1 < TOPK && incl1 >= TOPK) g_binB = base + 31 - lane;
    }
}

// =================== K3: compact + hist re-zero ============
__global__ void __launch_bounds__(256) compact_kernel(int N) {
    int gid = blockIdx.x * 256 + threadIdx.x;
    if (gid < N) {
        unsigned bits = __float_as_uint(g_score[gid]);
        if ((int)(bits >> 16) >= g_binB) {
            int pos = atomicAdd(&g_candcount, 1);
            if (pos < CAP)
                g_cand[pos] = ((ull)bits << 32) | (unsigned)(~gid);
        }
    }
    if (gid < HBINS) g_hist[gid] = 0;      // parallel re-zero for next replay
}

// bitonic shfl pass on a register-resident element (j <= 16, intra-warp)
__device__ __forceinline__ void shfl_pass(ull& v, int i, int j, int k) {
    ull wv = __shfl_xor_sync(0xFFFFFFFFu, v, j);
    bool desc  = ((i & k) == 0);
    bool lower = ((i & j) == 0);
    bool takeMax = (desc == lower);
    bool gt = v > wv;
    v = (takeMax == gt) ? v : wv;
}

// decode one winner's box (same arithmetic as reference path)
__device__ __forceinline__ void decode_one(
        int pos, ull key,
        const float4* __restrict__ prop,
        const float4* __restrict__ btp,
        int C, float W, float H)
{
    unsigned n = ~(unsigned)(key & 0xFFFFFFFFULL);
    if (n >= MAXN) n = 0;                  // defensive: never OOB
    int bc = (int)g_cls[n];
    float4 p = prop[n];
    float pw = p.z - p.x, ph = p.w - p.y;
    float pcx = p.x + 0.5f * pw, pcy = p.y + 0.5f * ph;
    float4 t = btp[(size_t)n * C + bc];
    float dcx = t.x * pw + pcx;
    float dcy = t.y * ph + pcy;
    float dw  = __expf(t.z) * pw;
    float dh  = __expf(t.w) * ph;
    float4 box;
    box.x = fminf(fmaxf(dcx - 0.5f * dw, 0.f), W);
    box.y = fminf(fmaxf(dcy - 0.5f * dh, 0.f), H);
    box.z = fminf(fmaxf(dcx + 0.5f * dw, 0.f), W);
    box.w = fminf(fmaxf(dcy + 0.5f * dh, 0.f), H);
    g_topboxes[pos] = box;
}

// =================== K4: bitonic sort + fused winner decode ===============
__global__ void __launch_bounds__(1024) sort_kernel(
        const float4* __restrict__ prop,
        const float4* __restrict__ btp,
        const int* __restrict__ ihp,
        const int* __restrict__ iwp,
        int C)
{
    extern __shared__ ull sk[];
    int t = threadIdx.x;
    int M = g_candcount; if (M > CAP) M = CAP;
    __syncthreads();                       // ALL threads read candcount first
    if (t == 0) g_candcount = 0;           // then reset for next replay

    int vi = ihp[0];
    float H = (vi > 0 && vi < 1000000) ? (float)vi : __int_as_float(vi);
    vi = iwp[0];
    float W = (vi > 0 && vi < 1000000) ? (float)vi : __int_as_float(vi);

    int P = 2048;
    while (P < M) P <<= 1;

    if (P == 2048) {
        const int i0 = t, i1 = t + 1024;
        ull v0 = (i0 < M) ? g_cand[i0] : 0ULL;
        ull v1 = (i1 < M) ? g_cand[i1] : 0ULL;
        #pragma unroll
        for (int k = 2; k <= 32; k <<= 1)
            #pragma unroll
            for (int j = k >> 1; j > 0; j >>= 1) {
                shfl_pass(v0, i0, j, k);
                shfl_pass(v1, i1, j, k);
            }
        for (int k = 64; k <= 2048; k <<= 1) {
            sk[i0] = v0; sk[i1] = v1;
            __syncthreads();
            for (int j = k >> 1; j >= 32; j >>= 1) {
                #pragma unroll
                for (int e = 0; e < 2; e++) {
                    int i = t + (e << 10);
                    int l = i ^ j;
                    if (l > i) {
                        bool desc = ((i & k) == 0);
                        ull a = sk[i], b = sk[l];
                        if (desc ? (a < b) : (a > b)) { sk[i] = b; sk[l] = a; }
                    }
                }
                __syncthreads();
            }
            v0 = sk[i0]; v1 = sk[i1];
            #pragma unroll
            for (int j = 16; j > 0; j >>= 1) {
                shfl_pass(v0, i0, j, k);
                shfl_pass(v1, i1, j, k);
            }
        }
        if (i0 < TOPK) decode_one(i0, v0, prop, btp, C, W, H);
        if (i1 < TOPK) decode_one(i1, v1, prop, btp, C, W, H);
    } else {
        int epw = P >> 10;
        for (int e = 0; e < epw; e++) {
            int i = t + (e << 10);
            sk[i] = (i < M) ? g_cand[i] : 0ULL;
        }
        __syncthreads();
        for (int k = 2; k <= P; k <<= 1)
            for (int j = k >> 1; j > 0; j >>= 1) {
                for (int e = 0; e < epw; e++) {
                    int i = t + (e << 10);
                    int l = i ^ j;
                    if (l > i) {
                        bool desc = ((i & k) == 0);
                        ull a = sk[i], b = sk[l];
                        if (desc ? (a < b) : (a > b)) { sk[i] = b; sk[l] = a; }
                    }
                }
                __syncthreads();
            }
        for (int i = t; i < TOPK; i += 1024)
            decode_one(i, sk[i], prop, btp, C, W, H);
    }
}

// =================== K5: NMS suppression bitmask (upper triangle only) =====
__global__ void __launch_bounds__(256) nms_mask_kernel() {
    __shared__ float4 sb[64];
    int cb  = blockIdx.x;
    int rby = blockIdx.y;
    if (cb * 64 + 63 < rby * 256) return;  // never consumed by the scan
    int t = threadIdx.x;
    int col0 = cb * 64;
    if (t < 64 && col0 + t < TOPK) sb[t] = g_topboxes[col0 + t];
    __syncthreads();
    int row = rby * 256 + t;
    if (row >= TOPK) return;
    float4 a = g_topboxes[row];
    float aarea = (a.z - a.x) * (a.w - a.y);
    ull bits = 0;
    int nj = min(64, TOPK - col0);
    for (int j = 0; j < nj; j++) {
        float4 b = sb[j];
        float lx = fmaxf(a.x, b.x), ly = fmaxf(a.y, b.y);
        float rx = fminf(a.z, b.z), ry = fminf(a.w, b.w);
        float iw = fmaxf(rx - lx, 0.f), ih = fmaxf(ry - ly, 0.f);
        float inter = iw * ih;
        float barea = (b.z - b.x) * (b.w - b.y);
        float iou = __fdividef(inter, aarea + barea - inter);
        if (iou > NMS_THR) bits |= (1ULL << j);   // NaN compares false
    }
    g_mask[row * CBLK + cb] = bits;
    if (cb == (row >> 6)) g_diag[row] = bits;     // diagonal word for the scan
}

// =================== K6: greedy scan (no shfl on chain) + final write =====
__global__ void __launch_bounds__(256) nms_final_kernel(float* __restrict__ out) {
    __shared__ ull skeep[CBLK];
    int t = threadIdx.x;
    if (t < 32) {
        ull rem = 0;        // lane t: OR of suppression for column block t
        ull cur_sup = 0;    // replicated: suppression word of current 64-row block
        ull kw = 0;
        ull bit = 1;
        const int D = 16;
        ull buf[D], dbuf[D];
        #pragma unroll
        for (int k = 0; k < D; k++) {
            buf[k]  = g_mask[k * CBLK + t];
            dbuf[k] = g_diag[k];           // broadcast load (all lanes same addr)
        }
        for (int i = 0; i < TOPK; i++) {
            ull cur = buf[i & (D - 1)];
            ull m0  = dbuf[i & (D - 1)];
            if (i + D < TOPK) {
                buf[i & (D - 1)]  = g_mask[(i + D) * CBLK + t];
                dbuf[i & (D - 1)] = g_diag[i + D];
            }

            bool keep = (cur_sup & bit) == 0ULL;
            if (keep) { cur_sup |= m0; kw |= bit; }
            rem |= keep ? cur : 0ULL;

            if ((i & 63) == 63) {
                if (t == 0) skeep[i >> 6] = kw;
                kw = 0; bit = 1;
                cur_sup = __shfl_sync(0xFFFFFFFFu, rem, (i + 1) >> 6);
            } else {
                bit <<= 1;
            }
        }
        if (t == 0) skeep[(TOPK - 1) >> 6] = kw;
    }
    __syncthreads();
    const float* tb = (const float*)g_topboxes;
    for (int idx = t; idx < TOPK * 4; idx += 256) {
        int r = idx >> 2;
        float k = ((skeep[r >> 6] >> (r & 63)) & 1ULL) ? 1.0f : 0.0f;
        out[idx] = tb[idx] * k;
    }
}

// ---------------- launcher: 6 graph nodes ----------------
extern "C" void kernel_launch(void* const* d_in, const int* in_sizes, int n_in,
                              void* d_out, int out_size)
{
    const float4* prop = (const float4*)d_in[0];
    const float4* btp  = (const float4*)d_in[1];
    const float*  cls  = (const float*)d_in[2];
    const float4* gt   = (const float4*)d_in[3];
    const int*    ih   = (const int*)d_in[4];
    const int*    iw   = (const int*)d_in[5];
    float*        out  = (float*)d_out;

    int N = in_sizes[0] / 4;
    int C = in_sizes[2] / N;
    int G = in_sizes[3] / 4;

    static int init_done = 0;
    if (!init_done) {
        cudaFuncSetAttribute(sort_kernel,
                             cudaFuncAttributeMaxDynamicSharedMemorySize,
                             CAP * (int)sizeof(ull));
        init_done = 1;
    }

    int gridP = (N + BM - 1) / BM;
    int smem_main = BM * 21 * (int)sizeof(float);

    main_kernel<<<gridP, BM, smem_main>>>(prop, cls, gt, ih, iw,
                                          (float4*)out, N, C, G);
    findbin_kernel<<<1, 1024>>>();
    compact_kernel<<<(N + 255) / 256, 256>>>(N);
    sort_kernel<<<1, 1024, CAP * sizeof(ull)>>>(prop, btp, ih, iw, C);

    dim3 grid((TOPK + 63) / 64, (TOPK + 255) / 256);
    nms_mask_kernel<<<grid, 256>>>();
    nms_final_kernel<<<1, 256>>>(out);
}

// round 15
// speedup vs baseline: 1.4757x; 1.0158x over previous
#include <cuda_runtime.h>
#include <cstdint>

#define TOPK      2000
#define NMS_THR   0.5f
#define MAXN      200000
#define MAXG      128
#define HBINS     65536
#define CAP       8192
#define CBLK      32          // ceil(TOPK/64)
#define BM        256         // threads per block in main kernel
#define ROWSPB    512         // proposals per block (two phases of BM)
#define NCELLMAX  128         // max grid cells (11x7=77 typical)
#define CELLCAP   32          // max GT entries per expanded cell list
#define DPF       16          // nms_final prefetch depth

typedef unsigned long long ull;

// ---------------- scratch (no allocation allowed) ----------------
__device__ float               g_score[MAXN];
__device__ unsigned char       g_cls[MAXN];
__device__ __align__(16) int   g_hist[HBINS];    // zero at load; re-zeroed in compact
__device__ int                 g_candcount;      // zero at load; reset in sort
__device__ int                 g_binB;
__device__ ull                 g_cand[CAP];
__device__ float4              g_topboxes[TOPK];
__device__ ull                 g_mask[(TOPK + DPF) * CBLK];  // padded for prefetch
__device__ ull                 g_diag[TOPK + DPF];           // padded for prefetch

// =================== K1: fused scores + reg_targets (two phases) ==========
__global__ void __launch_bounds__(BM) main_kernel(
        const float4* __restrict__ prop,
        const float*  __restrict__ cls,
        const float4* __restrict__ gt,
        const int* __restrict__ ihp,
        const int* __restrict__ iwp,
        float4* __restrict__ out,         // rows TOPK..TOPK+N
        int N, int C, int G)
{
    __shared__ float4        sgtb[MAXG];
    __shared__ float         sga[MAXG];
    __shared__ int           scnt[NCELLMAX];
    __shared__ unsigned char slist[NCELLMAX * CELLCAP];   // 4096 B, uint-aligned
    __shared__ int           soverflow;
    extern __shared__ float  scls[];      // BM*21 floats (stride 21 -> conflict-free)

    int tid = threadIdx.x;
    int b0  = blockIdx.x * ROWSPB;

    int vi = ihp[0];
    float H = (vi > 0 && vi < 1000000) ? (float)vi : __int_as_float(vi);
    vi = iwp[0];
    float W = (vi > 0 && vi < 1000000) ? (float)vi : __int_as_float(vi);

    int ncx = (int)((W + 127.0f) * 0.0078125f);
    int ncy = (int)((H + 127.0f) * 0.0078125f);
    bool useCells = (G <= MAXG) && (ncx >= 1) && (ncy >= 1) && (ncx * ncy <= NCELLMAX);

    for (int i = tid; i < G && i < MAXG; i += BM) {
        float4 g = gt[i];
        sgtb[i] = g;
        sga[i]  = (g.z - g.x) * (g.w - g.y);
    }
    if (tid < NCELLMAX) scnt[tid] = 0;
    if (tid == 0) soverflow = 0;
    __syncthreads();

    // expanded insertion: GT g goes into every cell whose probe cell could
    // reach it, i.e. cells [gx0-1 .. gx1] x [gy0-1 .. gy1]
    if (useCells && tid < G) {
        float4 g = sgtb[tid];
        int gx0 = max(0, min((int)(g.x * 0.0078125f) - 1, ncx - 1));
        int gx1 = max(0, min((int)(g.z * 0.0078125f),     ncx - 1));
        int gy0 = max(0, min((int)(g.y * 0.0078125f) - 1, ncy - 1));
        int gy1 = max(0, min((int)(g.w * 0.0078125f),     ncy - 1));
        for (int cy = gy0; cy <= gy1; cy++)
            for (int cx = gx0; cx <= gx1; cx++) {
                int cell = cy * ncx + cx;
                int pos = atomicAdd(&scnt[cell], 1);
                if (pos < CELLCAP) slist[cell * CELLCAP + pos] = (unsigned char)tid;
                else soverflow = 1;
            }
    }
    __syncthreads();

    #pragma unroll
    for (int half = 0; half < 2; half++) {
        int n0 = b0 + half * BM;
        int rows = min(BM, N - n0);
        if (rows <= 0) break;

        // stage cls rows (coalesced float4 reads when full phase)
        {
            const float* cbase = cls + (size_t)n0 * C;
            if (C == 21 && rows == BM) {
                const float4* c4 = (const float4*)cbase;
                float4* s4 = (float4*)scls;
                #pragma unroll
                for (int e = 0; e < 5; e++)
                    s4[tid + e * BM] = c4[tid + e * BM];
                {   int idx = tid + 5 * BM;
                    if (idx < BM * 21 / 4) s4[idx] = c4[idx];
                }
            } else {
                int total = rows * C;
                for (int idx = tid; idx < total; idx += BM) {
                    int r = idx / C;
                    scls[r * 21 + (idx - r * C)] = cbase[idx];
                }
            }
        }
        __syncthreads();

        int n = n0 + tid;
        if (n < N) {
            float4 p = prop[n];
            float pw = p.z - p.x, ph = p.w - p.y;
            float pcx = p.x + 0.5f * pw, pcy = p.y + 0.5f * ph;
            float parea = pw * ph;

            // softmax score + fg argmax (bit-identical to R12)
            const float* cr = scls + tid * 21;
            float m = cr[0], bl = -1e30f; int bc = 1;
            #pragma unroll
            for (int c = 1; c < 21; c++) {
                float v = cr[c];
                m = fmaxf(m, v);
                if (v > bl) { bl = v; bc = c; }
            }
            float Z = 0.f;
            #pragma unroll
            for (int c = 0; c < 21; c++) Z += __expf(cr[c] - m);
            float score = __fdividef(__expf(bl - m), Z);

            g_score[n] = score;
            g_cls[n]   = (unsigned char)bc;
            atomicAdd(&g_hist[__float_as_uint(score) >> 16], 1);

            // best-IoU gt match
            #define IOU_STEP(gg, nn, dd, ii)                                   \
                {   float4 gb = sgtb[(gg)];                                    \
                    float lx = fmaxf(gb.x, p.x);                               \
                    float ly = fmaxf(gb.y, p.y);                               \
                    float rx = fminf(gb.z, p.z);                               \
                    float ry = fminf(gb.w, p.w);                               \
                    float iw = fmaxf(rx - lx, 0.f), ihh = fmaxf(ry - ly, 0.f); \
                    float inter = iw * ihh;                                    \
                    float den = sga[(gg)] + parea - inter;                     \
                    if (inter * (dd) > (nn) * den) { (nn) = inter; (dd) = den; (ii) = (gg); } }
            int bg = 0;
            if (useCells && !soverflow) {
                float bnum = 0.f, bden = 1.f;
                int pcx0 = max(0, min((int)(p.x * 0.0078125f), ncx - 1));
                int pcy0 = max(0, min((int)(p.y * 0.0078125f), ncy - 1));
                int cell = pcy0 * ncx + pcx0;
                int cnt = min(scnt[cell], CELLCAP);
                const unsigned* lw = (const unsigned*)(slist + cell * CELLCAP);
                unsigned u[CELLCAP / 4];
                int nw = (cnt + 3) >> 2;
                for (int w2 = 0; w2 < nw; w2++) u[w2] = lw[w2];
                for (int k2 = 0; k2 < cnt; k2++) {
                    int g = (u[k2 >> 2] >> ((k2 & 3) * 8)) & 255;
                    IOU_STEP(g, bnum, bden, bg);
                }
            } else {
                float bnum = -1.f, bden = 1.f;
                for (int g = 0; g < G; g++) IOU_STEP(g, bnum, bden, bg);
            }
            #undef IOU_STEP

            float4 gb = sgtb[bg];
            float gw = gb.z - gb.x, gh = gb.w - gb.y;
            float gcx = gb.x + 0.5f * gw, gcy = gb.y + 0.5f * gh;
            float4 rt;
            rt.x = __fdividef(gcx - pcx, pw);
            rt.y = __fdividef(gcy - pcy, ph);
            rt.z = __logf(__fdividef(gw, pw));
            rt.w = __logf(__fdividef(gh, ph));
            out[TOPK + n] = rt;
        }
        __syncthreads();   // phase B re-stages scls
    }
}

// =================== K2: findbin ====
__global__ void __launch_bounds__(1024) findbin_kernel() {
    __shared__ int csum[1024];
    __shared__ int wsum[32];
    __shared__ int s_chunk, s_excl;
    int tid = threadIdx.x;
    int w = tid >> 5, lane = tid & 31;

    for (int c = w; c < 1024; c += 32) {
        int base = HBINS - (c + 1) * 64;
        int s = g_hist[base + lane] + g_hist[base + 32 + lane];
        s = __reduce_add_sync(0xFFFFFFFFu, s);
        if (lane == 0) csum[c] = s;
    }
    __syncthreads();

    int v = csum[tid];
    int x = v;
    #pragma unroll
    for (int o = 1; o < 32; o <<= 1) {
        int y = __shfl_up_sync(0xFFFFFFFFu, x, o);
        if (lane >= o) x += y;
    }
    if (lane == 31) wsum[w] = x;
    __syncthreads();
    if (w == 0) {
        int s = wsum[lane];
        #pragma unroll
        for (int o = 1; o < 32; o <<= 1) {
            int y = __shfl_up_sync(0xFFFFFFFFu, s, o);
            if (lane >= o) s += y;
        }
        wsum[lane] = s;
    }
    __syncthreads();
    int incl = x + ((w > 0) ? wsum[w - 1] : 0);
    int excl = incl - v;
    if (excl < TOPK && incl >= TOPK) { s_chunk = tid; s_excl = excl; }
    __syncthreads();

    if (w == 0) {
        int chunk = s_chunk, be = s_excl;
        int base = HBINS - (chunk + 1) * 64;
        int x0 = g_hist[base + 63 - lane];
        int x1 = g_hist[base + 31 - lane];
        int s0 = x0;
        #pragma unroll
        for (int o = 1; o < 32; o <<= 1) {
            int y = __shfl_up_sync(0xFFFFFFFFu, s0, o);
            if (lane >= o) s0 += y;
        }
        int t0 = __shfl_sync(0xFFFFFFFFu, s0, 31);
        int s1 = x1;
        #pragma unroll
        for (int o = 1; o < 32; o <<= 1) {
            int y = __shfl_up_sync(0xFFFFFFFFu, s1, o);
            if (lane >= o) s1 += y;
        }
        int incl0 = be + s0, excl0 = incl0 - x0;
        if (excl0 < TOPK && incl0 >= TOPK) g_binB = base + 63 - lane;
        int incl1 = be + t0 + s1, excl1 = incl1 - x1;
        if (excl1 < TOPK && incl1 >= TOPK) g_binB = base + 31 - lane;
    }
}

// =================== K3: compact + hist re-zero ============
__global__ void __launch_bounds__(256) compact_kernel(int N) {
    int gid = blockIdx.x * 256 + threadIdx.x;
    if (gid < N) {
        unsigned bits = __float_as_uint(g_score[gid]);
        if ((int)(bits >> 16) >= g_binB) {
            int pos = atomicAdd(&g_candcount, 1);
            if (pos < CAP)
                g_cand[pos] = ((ull)bits << 32) | (unsigned)(~gid);
        }
    }
    if (gid < HBINS) g_hist[gid] = 0;      // parallel re-zero for next replay
}

// bitonic shfl pass on a register-resident element (j <= 16, intra-warp)
__device__ __forceinline__ void shfl_pass(ull& v, int i, int j, int k) {
    ull wv = __shfl_xor_sync(0xFFFFFFFFu, v, j);
    bool desc  = ((i & k) == 0);
    bool lower = ((i & j) == 0);
    bool takeMax = (desc == lower);
    bool gt = v > wv;
    v = (takeMax == gt) ? v : wv;
}

// decode one winner's box (same arithmetic as reference path)
__device__ __forceinline__ void decode_one(
        int pos, ull key,
        const float4* __restrict__ prop,
        const float4* __restrict__ btp,
        int C, float W, float H)
{
    unsigned n = ~(unsigned)(key & 0xFFFFFFFFULL);
    if (n >= MAXN) n = 0;                  // defensive: never OOB
    int bc = (int)g_cls[n];
    float4 p = prop[n];
    float pw = p.z - p.x, ph = p.w - p.y;
    float pcx = p.x + 0.5f * pw, pcy = p.y + 0.5f * ph;
    float4 t = btp[(size_t)n * C + bc];
    float dcx = t.x * pw + pcx;
    float dcy = t.y * ph + pcy;
    float dw  = __expf(t.z) * pw;
    float dh  = __expf(t.w) * ph;
    float4 box;
    box.x = fminf(fmaxf(dcx - 0.5f * dw, 0.f), W);
    box.y = fminf(fmaxf(dcy - 0.5f * dh, 0.f), H);
    box.z = fminf(fmaxf(dcx + 0.5f * dw, 0.f), W);
    box.w = fminf(fmaxf(dcy + 0.5f * dh, 0.f), H);
    g_topboxes[pos] = box;
}

// =================== K4: bitonic sort + fused winner decode ===============
__global__ void __launch_bounds__(1024) sort_kernel(
        const float4* __restrict__ prop,
        const float4* __restrict__ btp,
        const int* __restrict__ ihp,
        const int* __restrict__ iwp,
        int C)
{
    extern __shared__ ull sk[];
    int t = threadIdx.x;
    int M = g_candcount; if (M > CAP) M = CAP;
    __syncthreads();                       // ALL threads read candcount first
    if (t == 0) g_candcount = 0;           // then reset for next replay

    int vi = ihp[0];
    float H = (vi > 0 && vi < 1000000) ? (float)vi : __int_as_float(vi);
    vi = iwp[0];
    float W = (vi > 0 && vi < 1000000) ? (float)vi : __int_as_float(vi);

    int P = 2048;
    while (P < M) P <<= 1;

    if (P == 2048) {
        const int i0 = t, i1 = t + 1024;
        ull v0 = (i0 < M) ? g_cand[i0] : 0ULL;
        ull v1 = (i1 < M) ? g_cand[i1] : 0ULL;
        #pragma unroll
        for (int k = 2; k <= 32; k <<= 1)
            #pragma unroll
            for (int j = k >> 1; j > 0; j >>= 1) {
                shfl_pass(v0, i0, j, k);
                shfl_pass(v1, i1, j, k);
            }
        for (int k = 64; k <= 2048; k <<= 1) {
            sk[i0] = v0; sk[i1] = v1;
            __syncthreads();
            for (int j = k >> 1; j >= 32; j >>= 1) {
                #pragma unroll
                for (int e = 0; e < 2; e++) {
                    int i = t + (e << 10);
                    int l = i ^ j;
                    if (l > i) {
                        bool desc = ((i & k) == 0);
                        ull a = sk[i], b = sk[l];
                        if (desc ? (a < b) : (a > b)) { sk[i] = b; sk[l] = a; }
                    }
                }
                __syncthreads();
            }
            v0 = sk[i0]; v1 = sk[i1];
            #pragma unroll
            for (int j = 16; j > 0; j >>= 1) {
                shfl_pass(v0, i0, j, k);
                shfl_pass(v1, i1, j, k);
            }
        }
        if (i0 < TOPK) decode_one(i0, v0, prop, btp, C, W, H);
        if (i1 < TOPK) decode_one(i1, v1, prop, btp, C, W, H);
    } else {
        int epw = P >> 10;
        for (int e = 0; e < epw; e++) {
            int i = t + (e << 10);
            sk[i] = (i < M) ? g_cand[i] : 0ULL;
        }
        __syncthreads();
        for (int k = 2; k <= P; k <<= 1)
            for (int j = k >> 1; j > 0; j >>= 1) {
                for (int e = 0; e < epw; e++) {
                    int i = t + (e << 10);
                    int l = i ^ j;
                    if (l > i) {
                        bool desc = ((i & k) == 0);
                        ull a = sk[i], b = sk[l];
                        if (desc ? (a < b) : (a > b)) { sk[i] = b; sk[l] = a; }
                    }
                }
                __syncthreads();
            }
        for (int i = t; i < TOPK; i += 1024)
            decode_one(i, sk[i], prop, btp, C, W, H);
    }
}

// =================== K5: NMS suppression bitmask (upper triangle only) =====
__global__ void __launch_bounds__(256) nms_mask_kernel() {
    __shared__ float4 sb[64];
    int cb  = blockIdx.x;
    int rby = blockIdx.y;
    if (cb * 64 + 63 < rby * 256) return;  // never consumed by the scan
    int t = threadIdx.x;
    int col0 = cb * 64;
    if (t < 64 && col0 + t < TOPK) sb[t] = g_topboxes[col0 + t];
    __syncthreads();
    int row = rby * 256 + t;
    if (row >= TOPK) return;
    float4 a = g_topboxes[row];
    float aarea = (a.z - a.x) * (a.w - a.y);
    ull bits = 0;
    int nj = min(64, TOPK - col0);
    for (int j = 0; j < nj; j++) {
        float4 b = sb[j];
        float lx = fmaxf(a.x, b.x), ly = fmaxf(a.y, b.y);
        float rx = fminf(a.z, b.z), ry = fminf(a.w, b.w);
        float iw = fmaxf(rx - lx, 0.f), ih = fmaxf(ry - ly, 0.f);
        float inter = iw * ih;
        float barea = (b.z - b.x) * (b.w - b.y);
        float iou = __fdividef(inter, aarea + barea - inter);
        if (iou > NMS_THR) bits |= (1ULL << j);   // NaN compares false
    }
    g_mask[row * CBLK + cb] = bits;
    if (cb == (row >> 6)) g_diag[row] = bits;     // diagonal word for the scan
}

// =================== K6: greedy scan (padded, unconditional prefetch) =====
__global__ void __launch_bounds__(256) nms_final_kernel(float* __restrict__ out) {
    __shared__ ull skeep[CBLK];
    int t = threadIdx.x;
    if (t < 32) {
        ull rem = 0;        // lane t: OR of suppression for column block t
        ull cur_sup = 0;    // replicated: suppression word of current 64-row block
        ull kw = 0;
        ull bit = 1;
        ull buf[DPF], dbuf[DPF];
        #pragma unroll
        for (int k = 0; k < DPF; k++) {
            buf[k]  = g_mask[k * CBLK + t];
            dbuf[k] = g_diag[k];           // broadcast load (all lanes same addr)
        }
        for (int i = 0; i < TOPK; i++) {
            ull cur = buf[i & (DPF - 1)];
            ull m0  = dbuf[i & (DPF - 1)];
            // padded arrays: always safe to prefetch i+DPF
            buf[i & (DPF - 1)]  = g_mask[(i + DPF) * CBLK + t];
            dbuf[i & (DPF - 1)] = g_diag[i + DPF];

            bool keep = (cur_sup & bit) == 0ULL;
            if (keep) { cur_sup |= m0; kw |= bit; }
            rem |= keep ? cur : 0ULL;

            if ((i & 63) == 63) {
                if (t == 0) skeep[i >> 6] = kw;
                kw = 0; bit = 1;
                cur_sup = __shfl_sync(0xFFFFFFFFu, rem, (i + 1) >> 6);
            } else {
                bit <<= 1;
            }
        }
        if (t == 0) skeep[(TOPK - 1) >> 6] = kw;
    }
    __syncthreads();
    const float* tb = (const float*)g_topboxes;
    for (int idx = t; idx < TOPK * 4; idx += 256) {
        int r = idx >> 2;
        float k = ((skeep[r >> 6] >> (r & 63)) & 1ULL) ? 1.0f : 0.0f;
        out[idx] = tb[idx] * k;
    }
}

// ---------------- launcher: 6 graph nodes ----------------
extern "C" void kernel_launch(void* const* d_in, const int* in_sizes, int n_in,
                              void* d_out, int out_size)
{
    const float4* prop = (const float4*)d_in[0];
    const float4* btp  = (const float4*)d_in[1];
    const float*  cls  = (const float*)d_in[2];
    const float4* gt   = (const float4*)d_in[3];
    const int*    ih   = (const int*)d_in[4];
    const int*    iw   = (const int*)d_in[5];
    float*        out  = (float*)d_out;

    int N = in_sizes[0] / 4;
    int C = in_sizes[2] / N;
    int G = in_sizes[3] / 4;

    static int init_done = 0;
    if (!init_done) {
        cudaFuncSetAttribute(sort_kernel,
                             cudaFuncAttributeMaxDynamicSharedMemorySize,
                             CAP * (int)sizeof(ull));
        init_done = 1;
    }

    int gridP = (N + ROWSPB - 1) / ROWSPB;
    int smem_main = BM * 21 * (int)sizeof(float);

    main_kernel<<<gridP, BM, smem_main>>>(prop, cls, gt, ih, iw,
                                          (float4*)out, N, C, G);
    findbin_kernel<<<1, 1024>>>();
    compact_kernel<<<(N + 255) / 256, 256>>>(N);
    sort_kernel<<<1, 1024, CAP * sizeof(ull)>>>(prop, btp, ih, iw, C);

    dim3 grid((TOPK + 63) / 64, (TOPK + 255) / 256);
    nms_mask_kernel<<<grid, 256>>>();
    nms_final_kernel<<<1, 256>>>(out);
}

// round 16
// speedup vs baseline: 1.4818x; 1.0041x over previous
#include <cuda_runtime.h>
#include <cstdint>

#define TOPK      2000
#define NMS_THR   0.5f
#define MAXN      200000
#define MAXG      128
#define HBINS     65536
#define CAP       8192
#define CBLK      32          // ceil(TOPK/64)
#define BM        256         // threads per block in main kernel
#define ROWSPB    512         // proposals per block (two phases of BM)
#define NCELLMAX  128         // max grid cells (11x7=77 typical)
#define CELLCAP   32          // max GT entries per expanded cell list
#define DPF       16          // nms_final prefetch depth

typedef unsigned long long ull;

// ---------------- scratch (no allocation allowed) ----------------
__device__ float               g_score[MAXN];
__device__ unsigned char       g_cls[MAXN];
__device__ __align__(16) int   g_hist[HBINS];    // zero at load; re-zeroed in compact
__device__ int                 g_candcount;      // zero at load; reset in sort
__device__ int                 g_binB;
__device__ ull                 g_cand[CAP];
__device__ float4              g_topboxes[TOPK];
__device__ ull                 g_mask[(TOPK + DPF) * CBLK];  // padded for prefetch
__device__ ull                 g_diag[TOPK + DPF];           // padded for prefetch

// =================== K1: fused scores + reg_targets (two phases) ==========
__global__ void __launch_bounds__(BM) main_kernel(
        const float4* __restrict__ prop,
        const float*  __restrict__ cls,
        const float4* __restrict__ gt,
        const int* __restrict__ ihp,
        const int* __restrict__ iwp,
        float4* __restrict__ out,         // rows TOPK..TOPK+N
        int N, int C, int G)
{
    __shared__ float4        sgtb[MAXG];
    __shared__ float         sga[MAXG];
    __shared__ int           scnt[NCELLMAX];
    __shared__ unsigned char slist[NCELLMAX * CELLCAP];   // 4096 B, uint-aligned
    __shared__ int           soverflow;
    extern __shared__ float  scls[];      // BM*21 floats (stride 21 -> conflict-free)

    int tid = threadIdx.x;
    int b0  = blockIdx.x * ROWSPB;

    int vi = ihp[0];
    float H = (vi > 0 && vi < 1000000) ? (float)vi : __int_as_float(vi);
    vi = iwp[0];
    float W = (vi > 0 && vi < 1000000) ? (float)vi : __int_as_float(vi);

    int ncx = (int)((W + 127.0f) * 0.0078125f);
    int ncy = (int)((H + 127.0f) * 0.0078125f);
    bool useCells = (G <= MAXG) && (ncx >= 1) && (ncy >= 1) && (ncx * ncy <= NCELLMAX);

    for (int i = tid; i < G && i < MAXG; i += BM) {
        float4 g = gt[i];
        sgtb[i] = g;
        sga[i]  = (g.z - g.x) * (g.w - g.y);
    }
    if (tid < NCELLMAX) scnt[tid] = 0;
    if (tid == 0) soverflow = 0;
    __syncthreads();

    // expanded insertion: GT g goes into every cell whose probe cell could
    // reach it, i.e. cells [gx0-1 .. gx1] x [gy0-1 .. gy1]
    if (useCells && tid < G) {
        float4 g = sgtb[tid];
        int gx0 = max(0, min((int)(g.x * 0.0078125f) - 1, ncx - 1));
        int gx1 = max(0, min((int)(g.z * 0.0078125f),     ncx - 1));
        int gy0 = max(0, min((int)(g.y * 0.0078125f) - 1, ncy - 1));
        int gy1 = max(0, min((int)(g.w * 0.0078125f),     ncy - 1));
        for (int cy = gy0; cy <= gy1; cy++)
            for (int cx = gx0; cx <= gx1; cx++) {
                int cell = cy * ncx + cx;
                int pos = atomicAdd(&scnt[cell], 1);
                if (pos < CELLCAP) slist[cell * CELLCAP + pos] = (unsigned char)tid;
                else soverflow = 1;
            }
    }
    __syncthreads();

    #pragma unroll
    for (int half = 0; half < 2; half++) {
        int n0 = b0 + half * BM;
        int rows = min(BM, N - n0);
        if (rows <= 0) break;

        // stage cls rows (coalesced float4 reads when full phase)
        {
            const float* cbase = cls + (size_t)n0 * C;
            if (C == 21 && rows == BM) {
                const float4* c4 = (const float4*)cbase;
                float4* s4 = (float4*)scls;
                #pragma unroll
                for (int e = 0; e < 5; e++)
                    s4[tid + e * BM] = c4[tid + e * BM];
                {   int idx = tid + 5 * BM;
                    if (idx < BM * 21 / 4) s4[idx] = c4[idx];
                }
            } else {
                int total = rows * C;
                for (int idx = tid; idx < total; idx += BM) {
                    int r = idx / C;
                    scls[r * 21 + (idx - r * C)] = cbase[idx];
                }
            }
        }
        __syncthreads();

        int n = n0 + tid;
        if (n < N) {
            float4 p = prop[n];
            float pw = p.z - p.x, ph = p.w - p.y;
            float pcx = p.x + 0.5f * pw, pcy = p.y + 0.5f * ph;
            float parea = pw * ph;

            // softmax score + fg argmax (bit-identical)
            const float* cr = scls + tid * 21;
            float m = cr[0], bl = -1e30f; int bc = 1;
            #pragma unroll
            for (int c = 1; c < 21; c++) {
                float v = cr[c];
                m = fmaxf(m, v);
                if (v > bl) { bl = v; bc = c; }
            }
            float Z = 0.f;
            #pragma unroll
            for (int c = 0; c < 21; c++) Z += __expf(cr[c] - m);
            float score = __fdividef(__expf(bl - m), Z);

            g_score[n] = score;
            g_cls[n]   = (unsigned char)bc;
            atomicAdd(&g_hist[__float_as_uint(score) >> 16], 1);

            // best-IoU gt match
            #define IOU_STEP(gg, nn, dd, ii)                                   \
                {   float4 gb = sgtb[(gg)];                                    \
                    float lx = fmaxf(gb.x, p.x);                               \
                    float ly = fmaxf(gb.y, p.y);                               \
                    float rx = fminf(gb.z, p.z);                               \
                    float ry = fminf(gb.w, p.w);                               \
                    float iw = fmaxf(rx - lx, 0.f), ihh = fmaxf(ry - ly, 0.f); \
                    float inter = iw * ihh;                                    \
                    float den = sga[(gg)] + parea - inter;                     \
                    if (inter * (dd) > (nn) * den) { (nn) = inter; (dd) = den; (ii) = (gg); } }
            int bg = 0;
            if (useCells && !soverflow) {
                float bnum = 0.f, bden = 1.f;
                int pcx0 = max(0, min((int)(p.x * 0.0078125f), ncx - 1));
                int pcy0 = max(0, min((int)(p.y * 0.0078125f), ncy - 1));
                int cell = pcy0 * ncx + pcx0;
                int cnt = min(scnt[cell], CELLCAP);
                const unsigned* lw = (const unsigned*)(slist + cell * CELLCAP);
                unsigned u[CELLCAP / 4];
                int nw = (cnt + 3) >> 2;
                for (int w2 = 0; w2 < nw; w2++) u[w2] = lw[w2];
                for (int k2 = 0; k2 < cnt; k2++) {
                    int g = (u[k2 >> 2] >> ((k2 & 3) * 8)) & 255;
                    IOU_STEP(g, bnum, bden, bg);
                }
            } else {
                float bnum = -1.f, bden = 1.f;
                for (int g = 0; g < G; g++) IOU_STEP(g, bnum, bden, bg);
            }
            #undef IOU_STEP

            float4 gb = sgtb[bg];
            float gw = gb.z - gb.x, gh = gb.w - gb.y;
            float gcx = gb.x + 0.5f * gw, gcy = gb.y + 0.5f * gh;
            float4 rt;
            rt.x = __fdividef(gcx - pcx, pw);
            rt.y = __fdividef(gcy - pcy, ph);
            rt.z = __logf(__fdividef(gw, pw));
            rt.w = __logf(__fdividef(gh, ph));
            out[TOPK + n] = rt;
        }
        __syncthreads();   // phase B re-stages scls
    }
}

// =================== K2: findbin (int4 chunk sums) ====
__global__ void __launch_bounds__(1024) findbin_kernel() {
    __shared__ int csum[1024];
    __shared__ int wsum[32];
    __shared__ int s_chunk, s_excl;
    int tid = threadIdx.x;
    int w = tid >> 5, lane = tid & 31;

    // chunk c = 64 bins = 16 int4; lanes 0..15 load one int4 each
    const int4* h4 = (const int4*)g_hist;
    for (int c = w; c < 1024; c += 32) {
        int base4 = (HBINS - (c + 1) * 64) >> 2;   // int4 index of chunk start
        int s = 0;
        if (lane < 16) {
            int4 v = h4[base4 + lane];
            s = v.x + v.y + v.z + v.w;
        }
        s = __reduce_add_sync(0xFFFFFFFFu, s);
        if (lane == 0) csum[c] = s;
    }
    __syncthreads();

    int v = csum[tid];
    int x = v;
    #pragma unroll
    for (int o = 1; o < 32; o <<= 1) {
        int y = __shfl_up_sync(0xFFFFFFFFu, x, o);
        if (lane >= o) x += y;
    }
    if (lane == 31) wsum[w] = x;
    __syncthreads();
    if (w == 0) {
        int s = wsum[lane];
        #pragma unroll
        for (int o = 1; o < 32; o <<= 1) {
            int y = __shfl_up_sync(0xFFFFFFFFu, s, o);
            if (lane >= o) s += y;
        }
        wsum[lane] = s;
    }
    __syncthreads();
    int incl = x + ((w > 0) ? wsum[w - 1] : 0);
    int excl = incl - v;
    if (excl < TOPK && incl >= TOPK) { s_chunk = tid; s_excl = excl; }
    __syncthreads();

    if (w == 0) {
        int chunk = s_chunk, be = s_excl;
        int base = HBINS - (chunk + 1) * 64;
        int x0 = g_hist[base + 63 - lane];
        int x1 = g_hist[base + 31 - lane];
        int s0 = x0;
        #pragma unroll
        for (int o = 1; o < 32; o <<= 1) {
            int y = __shfl_up_sync(0xFFFFFFFFu, s0, o);
            if (lane >= o) s0 += y;
        }
        int t0 = __shfl_sync(0xFFFFFFFFu, s0, 31);
        int s1 = x1;
        #pragma unroll
        for (int o = 1; o < 32; o <<= 1) {
            int y = __shfl_up_sync(0xFFFFFFFFu, s1, o);
            if (lane >= o) s1 += y;
        }
        int incl0 = be + s0, excl0 = incl0 - x0;
        if (excl0 < TOPK && incl0 >= TOPK) g_binB = base + 63 - lane;
        int incl1 = be + t0 + s1, excl1 = incl1 - x1;
        if (excl1 < TOPK && incl1 >= TOPK) g_binB = base + 31 - lane;
    }
}

// =================== K3: compact + hist re-zero ============
__global__ void __launch_bounds__(256) compact_kernel(int N) {
    int gid = blockIdx.x * 256 + threadIdx.x;
    if (gid < N) {
        unsigned bits = __float_as_uint(g_score[gid]);
        if ((int)(bits >> 16) >= g_binB) {
            int pos = atomicAdd(&g_candcount, 1);
            if (pos < CAP)
                g_cand[pos] = ((ull)bits << 32) | (unsigned)(~gid);
        }
    }
    if (gid < HBINS) g_hist[gid] = 0;      // parallel re-zero for next replay
}

// bitonic shfl pass on a register-resident element (j <= 16, intra-warp)
__device__ __forceinline__ void shfl_pass(ull& v, int i, int j, int k) {
    ull wv = __shfl_xor_sync(0xFFFFFFFFu, v, j);
    bool desc  = ((i & k) == 0);
    bool lower = ((i & j) == 0);
    bool takeMax = (desc == lower);
    bool gt = v > wv;
    v = (takeMax == gt) ? v : wv;
}

// =================== K4a: presort — bitonic stages k=2..512, 4 chunks =====
// Stage k only exchanges within k-aligned blocks, so stages k<=512 operate
// entirely inside each 512-element chunk: run them on 4 SMs in parallel.
// Direction uses the GLOBAL index i -> comparison network is bit-identical
// to the single-block version.
__global__ void __launch_bounds__(256) presort_kernel() {
    __shared__ ull sm[512];
    int t = threadIdx.x;
    int base = blockIdx.x * 512;
    int M = g_candcount; if (M > CAP) M = CAP;
    if (M > 2048) return;                  // sort_kernel's generic path handles

    const int i0 = base + t, i1 = base + t + 256;
    ull v0 = (i0 < M) ? g_cand[i0] : 0ULL;
    ull v1 = (i1 < M) ? g_cand[i1] : 0ULL;

    // stages k=2..32: fully intra-warp
    #pragma unroll
    for (int k = 2; k <= 32; k <<= 1)
        #pragma unroll
        for (int j = k >> 1; j > 0; j >>= 1) {
            shfl_pass(v0, i0, j, k);
            shfl_pass(v1, i1, j, k);
        }
    // stages k=64..512: j>=32 via smem, j<=16 via shfl
    for (int k = 64; k <= 512; k <<= 1) {
        sm[t] = v0; sm[t + 256] = v1;
        __syncthreads();
        for (int j = k >> 1; j >= 32; j >>= 1) {
            #pragma unroll
            for (int e = 0; e < 2; e++) {
                int i = base + t + (e << 8);
                int l = i ^ j;
                if (l > i) {
                    bool desc = ((i & k) == 0);
                    ull a = sm[i - base], b = sm[l - base];
                    if (desc ? (a < b) : (a > b)) { sm[i - base] = b; sm[l - base] = a; }
                }
            }
            __syncthreads();
        }
        v0 = sm[t]; v1 = sm[t + 256];
        #pragma unroll
        for (int j = 16; j > 0; j >>= 1) {
            shfl_pass(v0, i0, j, k);
            shfl_pass(v1, i1, j, k);
        }
    }
    g_cand[i0] = v0;                       // write back (includes zero padding)
    g_cand[i1] = v1;
}

// decode one winner's box (same arithmetic as reference path)
__device__ __forceinline__ void decode_one(
        int pos, ull key,
        const float4* __restrict__ prop,
        const float4* __restrict__ btp,
        int C, float W, float H)
{
    unsigned n = ~(unsigned)(key & 0xFFFFFFFFULL);
    if (n >= MAXN) n = 0;                  // defensive: never OOB
    int bc = (int)g_cls[n];
    float4 p = prop[n];
    float pw = p.z - p.x, ph = p.w - p.y;
    float pcx = p.x + 0.5f * pw, pcy = p.y + 0.5f * ph;
    float4 t = btp[(size_t)n * C + bc];
    float dcx = t.x * pw + pcx;
    float dcy = t.y * ph + pcy;
    float dw  = __expf(t.z) * pw;
    float dh  = __expf(t.w) * ph;
    float4 box;
    box.x = fminf(fmaxf(dcx - 0.5f * dw, 0.f), W);
    box.y = fminf(fmaxf(dcy - 0.5f * dh, 0.f), H);
    box.z = fminf(fmaxf(dcx + 0.5f * dw, 0.f), W);
    box.w = fminf(fmaxf(dcy + 0.5f * dh, 0.f), H);
    g_topboxes[pos] = box;
}

// =================== K4b: bitonic merge (k=1024,2048) + winner decode =====
__global__ void __launch_bounds__(1024) sort_kernel(
        const float4* __restrict__ prop,
        const float4* __restrict__ btp,
        const int* __restrict__ ihp,
        const int* __restrict__ iwp,
        int C)
{
    extern __shared__ ull sk[];
    int t = threadIdx.x;
    int M = g_candcount; if (M > CAP) M = CAP;
    __syncthreads();                       // ALL threads read candcount first
    if (t == 0) g_candcount = 0;           // then reset for next replay

    int vi = ihp[0];
    float H = (vi > 0 && vi < 1000000) ? (float)vi : __int_as_float(vi);
    vi = iwp[0];
    float W = (vi > 0 && vi < 1000000) ? (float)vi : __int_as_float(vi);

    if (M <= 2048) {
        // fast path: presort already ran stages k=2..512; continue k=1024,2048
        const int i0 = t, i1 = t + 1024;
        ull v0 = g_cand[i0];               // presort wrote all 2048 slots
        ull v1 = g_cand[i1];
        for (int k = 1024; k <= 2048; k <<= 1) {
            sk[i0] = v0; sk[i1] = v1;
            __syncthreads();
            for (int j = k >> 1; j >= 32; j >>= 1) {
                #pragma unroll
                for (int e = 0; e < 2; e++) {
                    int i = t + (e << 10);
                    int l = i ^ j;
                    if (l > i) {
                        bool desc = ((i & k) == 0);
                        ull a = sk[i], b = sk[l];
                        if (desc ? (a < b) : (a > b)) { sk[i] = b; sk[l] = a; }
                    }
                }
                __syncthreads();
            }
            v0 = sk[i0]; v1 = sk[i1];
            #pragma unroll
            for (int j = 16; j > 0; j >>= 1) {
                shfl_pass(v0, i0, j, k);
                shfl_pass(v1, i1, j, k);
            }
        }
        if (i0 < TOPK) decode_one(i0, v0, prop, btp, C, W, H);
        if (i1 < TOPK) decode_one(i1, v1, prop, btp, C, W, H);
    } else {
        // generic fallback: full sort (presort did nothing)
        int P = 2048;
        while (P < M) P <<= 1;
        int epw = P >> 10;
        for (int e = 0; e < epw; e++) {
            int i = t + (e << 10);
            sk[i] = (i < M) ? g_cand[i] : 0ULL;
        }
        __syncthreads();
        for (int k = 2; k <= P; k <<= 1)
            for (int j = k >> 1; j > 0; j >>= 1) {
                for (int e = 0; e < epw; e++) {
                    int i = t + (e << 10);
                    int l = i ^ j;
                    if (l > i) {
                        bool desc = ((i & k) == 0);
                        ull a = sk[i], b = sk[l];
                        if (desc ? (a < b) : (a > b)) { sk[i] = b; sk[l] = a; }
                    }
                }
                __syncthreads();
            }
        for (int i = t; i < TOPK; i += 1024)
            decode_one(i, sk[i], prop, btp, C, W, H);
    }
}

// =================== K5: NMS suppression bitmask (upper triangle only) =====
__global__ void __launch_bounds__(256) nms_mask_kernel() {
    __shared__ float4 sb[64];
    int cb  = blockIdx.x;
    int rby = blockIdx.y;
    if (cb * 64 + 63 < rby * 256) return;  // never consumed by the scan
    int t = threadIdx.x;
    int col0 = cb * 64;
    if (t < 64 && col0 + t < TOPK) sb[t] = g_topboxes[col0 + t];
    __syncthreads();
    int row = rby * 256 + t;
    if (row >= TOPK) return;
    float4 a = g_topboxes[row];
    float aarea = (a.z - a.x) * (a.w - a.y);
    ull bits = 0;
    int nj = min(64, TOPK - col0);
    for (int j = 0; j < nj; j++) {
        float4 b = sb[j];
        float lx = fmaxf(a.x, b.x), ly = fmaxf(a.y, b.y);
        float rx = fminf(a.z, b.z), ry = fminf(a.w, b.w);
        float iw = fmaxf(rx - lx, 0.f), ih = fmaxf(ry - ly, 0.f);
        float inter = iw * ih;
        float barea = (b.z - b.x) * (b.w - b.y);
        float iou = __fdividef(inter, aarea + barea - inter);
        if (iou > NMS_THR) bits |= (1ULL << j);   // NaN compares false
    }
    g_mask[row * CBLK + cb] = bits;
    if (cb == (row >> 6)) g_diag[row] = bits;     // diagonal word for the scan
}

// =================== K6: greedy scan (padded, unconditional prefetch) =====
__global__ void __launch_bounds__(256) nms_final_kernel(float* __restrict__ out) {
    __shared__ ull skeep[CBLK];
    int t = threadIdx.x;
    if (t < 32) {
        ull rem = 0;        // lane t: OR of suppression for column block t
        ull cur_sup = 0;    // replicated: suppression word of current 64-row block
        ull kw = 0;
        ull bit = 1;
        ull buf[DPF], dbuf[DPF];
        #pragma unroll
        for (int k = 0; k < DPF; k++) {
            buf[k]  = g_mask[k * CBLK + t];
            dbuf[k] = g_diag[k];           // broadcast load (all lanes same addr)
        }
        for (int i = 0; i < TOPK; i++) {
            ull cur = buf[i & (DPF - 1)];
            ull m0  = dbuf[i & (DPF - 1)];
            // padded arrays: always safe to prefetch i+DPF
            buf[i & (DPF - 1)]  = g_mask[(i + DPF) * CBLK + t];
            dbuf[i & (DPF - 1)] = g_diag[i + DPF];

            bool keep = (cur_sup & bit) == 0ULL;
            if (keep) { cur_sup |= m0; kw |= bit; }
            rem |= keep ? cur : 0ULL;

            if ((i & 63) == 63) {
                if (t == 0) skeep[i >> 6] = kw;
                kw = 0; bit = 1;
                cur_sup = __shfl_sync(0xFFFFFFFFu, rem, (i + 1) >> 6);
            } else {
                bit <<= 1;
            }
        }
        if (t == 0) skeep[(TOPK - 1) >> 6] = kw;
    }
    __syncthreads();
    const float* tb = (const float*)g_topboxes;
    for (int idx = t; idx < TOPK * 4; idx += 256) {
        int r = idx >> 2;
        float k = ((skeep[r >> 6] >> (r & 63)) & 1ULL) ? 1.0f : 0.0f;
        out[idx] = tb[idx] * k;
    }
}

// ---------------- launcher: 7 graph nodes ----------------
extern "C" void kernel_launch(void* const* d_in, const int* in_sizes, int n_in,
                              void* d_out, int out_size)
{
    const float4* prop = (const float4*)d_in[0];
    const float4* btp  = (const float4*)d_in[1];
    const float*  cls  = (const float*)d_in[2];
    const float4* gt   = (const float4*)d_in[3];
    const int*    ih   = (const int*)d_in[4];
    const int*    iw   = (const int*)d_in[5];
    float*        out  = (float*)d_out;

    int N = in_sizes[0] / 4;
    int C = in_sizes[2] / N;
    int G = in_sizes[3] / 4;

    static int init_done = 0;
    if (!init_done) {
        cudaFuncSetAttribute(sort_kernel,
                             cudaFuncAttributeMaxDynamicSharedMemorySize,
                             CAP * (int)sizeof(ull));
        init_done = 1;
    }

    int gridP = (N + ROWSPB - 1) / ROWSPB;
    int smem_main = BM * 21 * (int)sizeof(float);

    main_kernel<<<gridP, BM, smem_main>>>(prop, cls, gt, ih, iw,
                                          (float4*)out, N, C, G);
    findbin_kernel<<<1, 1024>>>();
    compact_kernel<<<(N + 255) / 256, 256>>>(N);
    presort_kernel<<<4, 256>>>();
    sort_kernel<<<1, 1024, CAP * sizeof(ull)>>>(prop, btp, ih, iw, C);

    dim3 grid((TOPK + 63) / 64, (TOPK + 255) / 256);
    nms_mask_kernel<<<grid, 256>>>();
    nms_final_kernel<<<1, 256>>>(out);
}